// round 12
// baseline (speedup 1.0000x reference)
#include <cuda_runtime.h>
#include <cuda_bf16.h>
#include <stdint.h>
#include <math.h>

#define BATCH 2
#define SEQ   2048
#define DIM   1024
#define ROWS  (BATCH*SEQ)   // 4096
#define NH    16
#define DH    64

// Scratch (allocation-free rule: __device__ globals)
__device__ float g_qkv[3*ROWS*DIM];          // Q,K,V fp32 outputs
__device__ float g_sinT[SEQ*32];             // RoPE tables [pos][i]
__device__ float g_cosT[SEQ*32];
__device__ __nv_bfloat16 g_ah[ROWS*DIM];     // x_norm split hi; later attn-out hi
__device__ __nv_bfloat16 g_al[ROWS*DIM];     // x_norm split lo; later attn-out lo
__device__ __nv_bfloat16 g_th[4*DIM*DIM];    // W^T split hi [4][N][K] (q,k,v,o)
__device__ __nv_bfloat16 g_tl[4*DIM*DIM];    // W^T split lo
// attention operands, head-contiguous layouts
__device__ __nv_bfloat16 g_qh[ROWS*DIM];     // Q hi (roped) [bh][s][d]
__device__ __nv_bfloat16 g_ql[ROWS*DIM];
__device__ __nv_bfloat16 g_kh[ROWS*DIM];     // K hi (roped) [bh][s][d]
__device__ __nv_bfloat16 g_kl[ROWS*DIM];
__device__ __nv_bfloat16 g_vth[ROWS*DIM];    // V^T hi [bh][d][s]
__device__ __nv_bfloat16 g_vtl[ROWS*DIM];

// ===========================================================================
// Portable (compute_103-safe) PTX helpers: mma.sync / ldmatrix / cp.async
// ===========================================================================
__device__ __forceinline__ uint32_t smem_u32(const void* p) {
    uint32_t a;
    asm("{ .reg .u64 t; cvta.to.shared.u64 t, %1; cvt.u32.u64 %0, t; }"
        : "=r"(a) : "l"(p));
    return a;
}
__device__ __forceinline__ void cp_async16(uint32_t saddr, const void* gaddr) {
    asm volatile("cp.async.cg.shared.global [%0], [%1], 16;"
                 :: "r"(saddr), "l"(gaddr));
}
__device__ __forceinline__ void cp_commit() {
    asm volatile("cp.async.commit_group;" ::: "memory");
}
__device__ __forceinline__ void ldsm4(uint32_t* r, uint32_t addr) {
    asm volatile("ldmatrix.sync.aligned.m8n8.x4.shared.b16 {%0,%1,%2,%3}, [%4];"
                 : "=r"(r[0]), "=r"(r[1]), "=r"(r[2]), "=r"(r[3]) : "r"(addr));
}
__device__ __forceinline__ void mma16816(float* c, const uint32_t* a,
                                         uint32_t b0, uint32_t b1) {
    asm volatile(
        "mma.sync.aligned.m16n8k16.row.col.f32.bf16.bf16.f32 "
        "{%0,%1,%2,%3}, {%4,%5,%6,%7}, {%8,%9}, {%0,%1,%2,%3};"
        : "+f"(c[0]), "+f"(c[1]), "+f"(c[2]), "+f"(c[3])
        : "r"(a[0]), "r"(a[1]), "r"(a[2]), "r"(a[3]), "r"(b0), "r"(b1));
}
__device__ __forceinline__ uint32_t pack2h(__nv_bfloat16 a, __nv_bfloat16 b) {
    __nv_bfloat162 t = __halves2bfloat162(a, b);
    return *reinterpret_cast<uint32_t*>(&t);
}
__device__ __forceinline__ uint32_t pack2f(float a, float b) {
    __nv_bfloat162 t = __floats2bfloat162_rn(a, b);
    return *reinterpret_cast<uint32_t*>(&t);
}
__device__ __forceinline__ void split2(float a, float b, uint32_t& hi, uint32_t& lo) {
    __nv_bfloat16 ha = __float2bfloat16(a), hb = __float2bfloat16(b);
    hi = pack2h(ha, hb);
    lo = pack2f(a - __bfloat162float(ha), b - __bfloat162float(hb));
}
// exp(x*0.125) as a single FMUL + MUFU: ex2(x * 0.125*log2(e))
__device__ __forceinline__ float expq(float x) {
    float y;
    asm("ex2.approx.ftz.f32 %0, %1;" : "=f"(y) : "f"(x * 0.1803368801111244f));
    return y;
}

// ===========================================================================
// MERGED prologue: one launch does everything independent of the QKV GEMM.
//   z in [0,4): transpose+split weight z
//   z == 4   : RoPE sin/cos table
//   z in [5,9): RMSNorm + bf16 split, rows (z-5)*1024 + by*32 + bx
// ===========================================================================
__global__ __launch_bounds__(256) void prologue_kernel(
    const float* __restrict__ x, const float* __restrict__ sc,
    const float* __restrict__ W0, const float* __restrict__ W1,
    const float* __restrict__ W2, const float* __restrict__ W3,
    __nv_bfloat16* __restrict__ Th, __nv_bfloat16* __restrict__ Tl,
    float* __restrict__ sinT, float* __restrict__ cosT,
    __nv_bfloat16* __restrict__ ah, __nv_bfloat16* __restrict__ al)
{
    __shared__ float tile[32][33];
    __shared__ float red[256];
    int z = blockIdx.z;

    if (z == 4) {
        int idx = (blockIdx.y * 32 + blockIdx.x) * 256 + threadIdx.x;
        if (idx < SEQ * 32) {
            int pos = idx >> 5, i = idx & 31;
            float e = (2.0f * (float)i) / (float)DH;
            float theta = exp2f(-e * 19.931568569324174f);   // 1e6^-e
            float ang = (float)pos * theta;
            sinT[idx] = sinf(ang);
            cosT[idx] = cosf(ang);
        }
        return;
    }

    if (z >= 5) {
        int row = (z - 5) * 1024 + blockIdx.y * 32 + blockIdx.x;
        const float* xr = x + (size_t)row * DIM;
        float v[4];
        float ss = 0.f;
        #pragma unroll
        for (int j = 0; j < 4; j++) {
            v[j] = xr[threadIdx.x + j * 256];
            ss = fmaf(v[j], v[j], ss);
        }
        red[threadIdx.x] = ss;
        __syncthreads();
        #pragma unroll
        for (int s = 128; s > 0; s >>= 1) {
            if (threadIdx.x < s) red[threadIdx.x] += red[threadIdx.x + s];
            __syncthreads();
        }
        float r = rsqrtf(red[0] * (1.0f / DIM) + 1e-6f);
        #pragma unroll
        for (int j = 0; j < 4; j++) {
            int i = threadIdx.x + j * 256;
            float y = v[j] * r * sc[i];
            __nv_bfloat16 h = __float2bfloat16(y);
            ah[(size_t)row * DIM + i] = h;
            al[(size_t)row * DIM + i] = __float2bfloat16(y - __bfloat162float(h));
        }
        return;
    }

    const float* W = (z == 0) ? W0 : (z == 1) ? W1 : (z == 2) ? W2 : W3;
    __nv_bfloat16* th = Th + (size_t)z * DIM * DIM;
    __nv_bfloat16* tl = Tl + (size_t)z * DIM * DIM;

    int k0 = blockIdx.y * 32, n0 = blockIdx.x * 32;
    int tx = threadIdx.x & 31, ty = threadIdx.x >> 5;   // 32 x 8
    #pragma unroll
    for (int i = 0; i < 32; i += 8)
        tile[ty + i][tx] = W[(size_t)(k0 + ty + i) * DIM + n0 + tx];
    __syncthreads();
    #pragma unroll
    for (int i = 0; i < 32; i += 8) {
        float v = tile[tx][ty + i];    // = W[k0+tx][n0+ty+i]
        __nv_bfloat16 h = __float2bfloat16(v);
        float r = v - __bfloat162float(h);
        size_t o = (size_t)(n0 + ty + i) * DIM + k0 + tx;
        th[o] = h;
        tl[o] = __float2bfloat16(r);
    }
}

// ===========================================================================
// bf16-split GEMM via mma.sync. 3-stage cp.async pipeline (validated R10).
// ===========================================================================
#define A_TILE_B 20480             // 256 rows x 80 bytes
#define B_TILE_B 10240             // 128 rows x 80 bytes
#define STG_B    (2*A_TILE_B + 2*B_TILE_B)   // 61440
#define GEMM_SMEM (3*STG_B)                   // 184320 (3 stages)

__global__ __launch_bounds__(256) void mma_gemm_kernel(
    const __nv_bfloat16* __restrict__ Ah, const __nv_bfloat16* __restrict__ Al,
    const __nv_bfloat16* __restrict__ BhBase, const __nv_bfloat16* __restrict__ BlBase,
    float* __restrict__ CBase)
{
    extern __shared__ char smem[];
    uint32_t sb = smem_u32(smem);

    const int tid  = threadIdx.x;
    const int lane = tid & 31;
    const int wid  = tid >> 5;
    const int warp_m = wid & 3;
    const int warp_n = wid >> 2;
    const int which = blockIdx.x >> 3;               // weight index
    const int bm = blockIdx.y * 256;
    const int bn = (blockIdx.x & 7) * 128;

    const __nv_bfloat16* Bh = BhBase + (size_t)which * DIM * DIM;
    const __nv_bfloat16* Bl = BlBase + (size_t)which * DIM * DIM;
    float* C = CBase + (size_t)which * ROWS * DIM;

    float acc[4][8][4];
    #pragma unroll
    for (int i = 0; i < 4; i++)
        #pragma unroll
        for (int j = 0; j < 8; j++)
            #pragma unroll
            for (int q = 0; q < 4; q++) acc[i][j][q] = 0.f;

    auto load_stage = [&](int kt, int s) {
        const __nv_bfloat16* asrc[2] = {Ah, Al};
        #pragma unroll
        for (int t = 0; t < 2; t++) {
            #pragma unroll
            for (int i = 0; i < 4; i++) {
                int chunk = tid + i * 256;         // 0..1023
                int row = chunk >> 2, c = chunk & 3;
                cp_async16(sb + s * STG_B + t * A_TILE_B + row * 80 + c * 16,
                           asrc[t] + (size_t)(bm + row) * DIM + kt * 32 + c * 8);
            }
        }
        const __nv_bfloat16* bsrc[2] = {Bh, Bl};
        #pragma unroll
        for (int t = 0; t < 2; t++) {
            #pragma unroll
            for (int i = 0; i < 2; i++) {
                int chunk = tid + i * 256;         // 0..511
                int row = chunk >> 2, c = chunk & 3;
                cp_async16(sb + s * STG_B + 2 * A_TILE_B + t * B_TILE_B + row * 80 + c * 16,
                           bsrc[t] + (size_t)(bn + row) * DIM + kt * 32 + c * 8);
            }
        }
        cp_commit();
    };

    load_stage(0, 0);
    load_stage(1, 1);

    const int aRow = lane & 15;
    const int aK16 = (lane >> 4) * 16;
    const int bRow = (lane & 7) + ((lane >> 4) << 3);
    const int bK16 = ((lane >> 3) & 1) * 16;

    int sNext = 2;   // stage index for kt+2
    for (int kt = 0; kt < 32; kt++) {
        if (kt < 31) asm volatile("cp.async.wait_group 1;" ::: "memory");
        else         asm volatile("cp.async.wait_group 0;" ::: "memory");
        __syncthreads();

        if (kt + 2 < 32) load_stage(kt + 2, sNext);

        int sCur = sNext + 1; if (sCur >= 3) sCur -= 3;   // == kt % 3
        uint32_t st  = sb + sCur * STG_B;
        uint32_t aHb = st + (warp_m * 64 + aRow) * 80 + aK16;
        uint32_t aLb = aHb + A_TILE_B;
        uint32_t bHb = st + 2 * A_TILE_B + (warp_n * 64 + bRow) * 80 + bK16;
        uint32_t bLb = bHb + B_TILE_B;
        sNext = sCur;

        #pragma unroll
        for (int ks = 0; ks < 2; ks++) {
            uint32_t koff = ks * 32;
            uint32_t fah[4][4], fal[4][4], fb[4][4];
            #pragma unroll
            for (int mt = 0; mt < 4; mt++) {
                ldsm4(fah[mt], aHb + mt * 1280 + koff);
                ldsm4(fal[mt], aLb + mt * 1280 + koff);
            }
            #pragma unroll
            for (int n2 = 0; n2 < 4; n2++)
                ldsm4(fb[n2], bHb + n2 * 1280 + koff);
            #pragma unroll
            for (int mt = 0; mt < 4; mt++)
                #pragma unroll
                for (int nt = 0; nt < 8; nt++)
                    mma16816(acc[mt][nt], fah[mt],
                             fb[nt >> 1][(nt & 1) * 2], fb[nt >> 1][(nt & 1) * 2 + 1]);
            #pragma unroll
            for (int mt = 0; mt < 4; mt++)
                #pragma unroll
                for (int nt = 0; nt < 8; nt++)
                    mma16816(acc[mt][nt], fal[mt],
                             fb[nt >> 1][(nt & 1) * 2], fb[nt >> 1][(nt & 1) * 2 + 1]);
            #pragma unroll
            for (int n2 = 0; n2 < 4; n2++)
                ldsm4(fb[n2], bLb + n2 * 1280 + koff);
            #pragma unroll
            for (int mt = 0; mt < 4; mt++)
                #pragma unroll
                for (int nt = 0; nt < 8; nt++)
                    mma16816(acc[mt][nt], fah[mt],
                             fb[nt >> 1][(nt & 1) * 2], fb[nt >> 1][(nt & 1) * 2 + 1]);
        }
    }

    const int g = lane >> 2, t2 = (lane & 3) * 2;
    #pragma unroll
    for (int mt = 0; mt < 4; mt++) {
        #pragma unroll
        for (int nt = 0; nt < 8; nt++) {
            int row = bm + warp_m * 64 + mt * 16 + g;
            int col = bn + warp_n * 64 + nt * 8 + t2;
            *(float2*)&C[(size_t)row * DIM + col] =
                make_float2(acc[mt][nt][0], acc[mt][nt][1]);
            *(float2*)&C[(size_t)(row + 8) * DIM + col] =
                make_float2(acc[mt][nt][2], acc[mt][nt][3]);
        }
    }
}

// ===========================================================================
// Merged RoPE-split (float4 vectorized) + V transpose-split (4B stores).
// ===========================================================================
__global__ __launch_bounds__(256) void qkv_prep_kernel(
    const float* __restrict__ qkv,
    const float* __restrict__ sinT, const float* __restrict__ cosT,
    __nv_bfloat16* __restrict__ Qh, __nv_bfloat16* __restrict__ Ql,
    __nv_bfloat16* __restrict__ Kh, __nv_bfloat16* __restrict__ Kl,
    __nv_bfloat16* __restrict__ Vth, __nv_bfloat16* __restrict__ Vtl)
{
    __shared__ float tile[32][33];
    int bid = blockIdx.x;

    if (bid < 4096) {
        int idx = bid * 256 + threadIdx.x;     // 2^20 total
        int which = idx >> 19;                 // 0=q, 1=k
        int r   = idx & ((1 << 19) - 1);
        int row = r >> 7;                      // 128 = 16 heads * 8
        int rem = r & 127;
        int head = rem >> 3;
        int i4   = (rem & 7) * 4;

        const float* src = qkv + (size_t)which * ROWS * DIM
                               + (size_t)row * DIM + head * DH;
        int pos = row & (SEQ - 1);

        float4 sn = *(const float4*)&sinT[pos * 32 + i4];
        float4 cs = *(const float4*)&cosT[pos * 32 + i4];
        float4 x1 = *(const float4*)&src[i4];
        float4 x2 = *(const float4*)&src[i4 + 32];

        float y1a = x1.x * cs.x - x2.x * sn.x, y2a = x1.x * sn.x + x2.x * cs.x;
        float y1b = x1.y * cs.y - x2.y * sn.y, y2b = x1.y * sn.y + x2.y * cs.y;
        float y1c = x1.z * cs.z - x2.z * sn.z, y2c = x1.z * sn.z + x2.z * cs.z;
        float y1d = x1.w * cs.w - x2.w * sn.w, y2d = x1.w * sn.w + x2.w * cs.w;

        int b = row >> 11, s = row & (SEQ - 1);
        size_t o = ((size_t)(b * NH + head) * SEQ + s) * DH + i4;
        __nv_bfloat16* H = which ? Kh : Qh;
        __nv_bfloat16* L = which ? Kl : Ql;
        uint32_t h0, l0, h1, l1;
        split2(y1a, y1b, h0, l0);
        split2(y1c, y1d, h1, l1);
        *(uint2*)&H[o] = make_uint2(h0, h1);
        *(uint2*)&L[o] = make_uint2(l0, l1);
        split2(y2a, y2b, h0, l0);
        split2(y2c, y2d, h1, l1);
        *(uint2*)&H[o + 32] = make_uint2(h0, h1);
        *(uint2*)&L[o + 32] = make_uint2(l0, l1);
    } else {
        int b2 = bid - 4096;                 // [0, 4096)
        int s0 = (b2 & 63) * 32;
        int d0 = ((b2 >> 6) & 1) * 32;
        int bh = b2 >> 7;
        int b = bh >> 4, h = bh & 15;
        const float* v = qkv + (size_t)2 * ROWS * DIM;
        int tx = threadIdx.x & 31, ty = threadIdx.x >> 5;
        #pragma unroll
        for (int i = 0; i < 32; i += 8)
            tile[ty + i][tx] = v[(size_t)(b * SEQ + s0 + ty + i) * DIM + h * DH + d0 + tx];
        __syncthreads();
        int sx = threadIdx.x & 15;
        int dy = threadIdx.x >> 4;
        #pragma unroll
        for (int dd = 0; dd < 32; dd += 16) {
            int d = dy + dd;
            float va = tile[sx * 2][d];
            float vb = tile[sx * 2 + 1][d];
            uint32_t hi, lo;
            split2(va, vb, hi, lo);
            size_t o = ((size_t)(bh * DH + d0 + d)) * SEQ + s0 + sx * 2;
            *(uint32_t*)&Vth[o] = hi;
            *(uint32_t*)&Vtl[o] = lo;
        }
    }
}

// ===========================================================================
// Flash attention via mma.sync, split-bf16, 3-stage KV pipeline.
// Softmax: warp-uniform causal fast path + single-FMUL exp.
// ===========================================================================
#define FP      144                 // smem row pitch (bytes)
#define FQ_OFF  0
#define FK_OFF  36864
#define FV_OFF  92160
#define FL_SMEM 147456

__global__ __launch_bounds__(256) void flash_mma_kernel(
    const __nv_bfloat16* __restrict__ Qh_, const __nv_bfloat16* __restrict__ Ql_,
    const __nv_bfloat16* __restrict__ Kh_, const __nv_bfloat16* __restrict__ Kl_,
    const __nv_bfloat16* __restrict__ Vth_, const __nv_bfloat16* __restrict__ Vtl_,
    __nv_bfloat16* __restrict__ Oh, __nv_bfloat16* __restrict__ Ol)
{
    extern __shared__ char smem[];
    uint32_t sb = smem_u32(smem);
    const int tid = threadIdx.x, lane = tid & 31, wid = tid >> 5;
    const int bh = blockIdx.y;
    const int qt = (gridDim.x - 1) - blockIdx.x;   // heavy tiles first
    const int nkt = 2 * (qt + 1);                  // 64-key chunks
    const size_t qkoff = (size_t)bh * SEQ * DH;
    const size_t voff  = (size_t)bh * DH * SEQ;

    // Q tile load (once)
    {
        const __nv_bfloat16* qs[2] = {Qh_ + qkoff, Ql_ + qkoff};
        #pragma unroll
        for (int i = 0; i < 8; i++) {
            int idx = tid + i * 256;           // 0..2047
            int t = idx >> 10, rem = idx & 1023;
            int row = rem >> 3, c = rem & 7;
            cp_async16(sb + FQ_OFF + t * 18432 + row * FP + c * 16,
                       qs[t] + (size_t)(qt * 128 + row) * DH + c * 8);
        }
        cp_commit();
    }

    auto load_kv = [&](int kt, int s) {
        int k0 = kt * 64;
        const __nv_bfloat16* ks_[2] = {Kh_ + qkoff, Kl_ + qkoff};
        const __nv_bfloat16* vs_[2] = {Vth_ + voff, Vtl_ + voff};
        #pragma unroll
        for (int i = 0; i < 4; i++) {
            int idx = tid + i * 256;           // 0..1023
            int t = idx >> 9, rem = idx & 511;
            int row = rem >> 3, c = rem & 7;
            cp_async16(sb + FK_OFF + s * 18432 + t * 9216 + row * FP + c * 16,
                       ks_[t] + (size_t)(k0 + row) * DH + c * 8);
        }
        #pragma unroll
        for (int i = 0; i < 4; i++) {
            int idx = tid + i * 256;
            int t = idx >> 9, rem = idx & 511;
            int row = rem >> 3, c = rem & 7;   // row = dh index, c = key chunk
            cp_async16(sb + FV_OFF + s * 18432 + t * 9216 + row * FP + c * 16,
                       vs_[t] + (size_t)row * SEQ + k0 + c * 8);
        }
        cp_commit();
    };
    load_kv(0, 0);
    load_kv(1, 1);

    const int g = lane >> 2, t2 = (lane & 3) * 2;
    const int aRow = lane & 15, aK16 = (lane >> 4) * 16;
    const int bRow = (lane & 7) + ((lane >> 4) << 3);
    const int bK16 = ((lane >> 3) & 1) * 16;

    asm volatile("cp.async.wait_group 2;" ::: "memory");
    __syncthreads();

    uint32_t qh[4][4], ql[4][4];
    {
        uint32_t base = sb + FQ_OFF + (wid * 16 + aRow) * FP + aK16;
        #pragma unroll
        for (int ks = 0; ks < 4; ks++) {
            ldsm4(qh[ks], base + ks * 32);
            ldsm4(ql[ks], base + 18432 + ks * 32);
        }
    }

    float o[8][4];
    #pragma unroll
    for (int nt = 0; nt < 8; nt++)
        #pragma unroll
        for (int j = 0; j < 4; j++) o[nt][j] = 0.f;
    float l0 = 0.f, l1 = 0.f;
    const int row0 = qt * 128 + wid * 16 + g;
    const int rowWarpMin = qt * 128 + wid * 16;   // warp-uniform

    int sNext = 2;
    for (int kt = 0; kt < nkt; kt++) {
        if (kt < nkt - 1) asm volatile("cp.async.wait_group 1;" ::: "memory");
        else              asm volatile("cp.async.wait_group 0;" ::: "memory");
        __syncthreads();

        if (kt + 2 < nkt) load_kv(kt + 2, sNext);

        int sCur = sNext + 1; if (sCur >= 3) sCur -= 3;   // == kt % 3
        uint32_t stK = sb + FK_OFF + sCur * 18432;
        uint32_t stV = sb + FV_OFF + sCur * 18432;
        sNext = sCur;

        float S[8][4];
        #pragma unroll
        for (int nt = 0; nt < 8; nt++)
            #pragma unroll
            for (int j = 0; j < 4; j++) S[nt][j] = 0.f;

        #pragma unroll
        for (int ks = 0; ks < 4; ks++) {
            uint32_t fkh[4][4], fkl[4][4];
            #pragma unroll
            for (int n2 = 0; n2 < 4; n2++) {
                uint32_t a = stK + (n2 * 16 + bRow) * FP + bK16 + ks * 32;
                ldsm4(fkh[n2], a);
                ldsm4(fkl[n2], a + 9216);
            }
            #pragma unroll
            for (int nt = 0; nt < 8; nt++) {
                mma16816(S[nt], qh[ks], fkh[nt >> 1][(nt & 1) * 2], fkh[nt >> 1][(nt & 1) * 2 + 1]);
                mma16816(S[nt], qh[ks], fkl[nt >> 1][(nt & 1) * 2], fkl[nt >> 1][(nt & 1) * 2 + 1]);
                mma16816(S[nt], ql[ks], fkh[nt >> 1][(nt & 1) * 2], fkh[nt >> 1][(nt & 1) * 2 + 1]);
            }
        }

        // ---- softmax + pack P; warp-uniform fast path when chunk fully
        //      visible to every row this warp owns (predicates all true) ----
        uint32_t pah[4][4], pal[4][4];
        int k0 = kt * 64;
        if (k0 + 63 <= rowWarpMin) {
            #pragma unroll
            for (int nt = 0; nt < 8; nt++) {
                float p0 = expq(S[nt][0]);
                float p1 = expq(S[nt][1]);
                float p2 = expq(S[nt][2]);
                float p3 = expq(S[nt][3]);
                l0 += p0 + p1;
                l1 += p2 + p3;
                __nv_bfloat16 h0 = __float2bfloat16(p0), h1 = __float2bfloat16(p1);
                __nv_bfloat16 h2 = __float2bfloat16(p2), h3 = __float2bfloat16(p3);
                float r0 = p0 - __bfloat162float(h0), r1 = p1 - __bfloat162float(h1);
                float r2 = p2 - __bfloat162float(h2), r3 = p3 - __bfloat162float(h3);
                int ks2 = nt >> 1, off = (nt & 1) * 2;
                pah[ks2][off]     = pack2h(h0, h1);
                pah[ks2][off + 1] = pack2h(h2, h3);
                pal[ks2][off]     = pack2f(r0, r1);
                pal[ks2][off + 1] = pack2f(r2, r3);
            }
        } else {
            #pragma unroll
            for (int nt = 0; nt < 8; nt++) {
                int col = k0 + nt * 8 + t2;
                float p0 = (col     <= row0)     ? expq(S[nt][0]) : 0.f;
                float p1 = (col + 1 <= row0)     ? expq(S[nt][1]) : 0.f;
                float p2 = (col     <= row0 + 8) ? expq(S[nt][2]) : 0.f;
                float p3 = (col + 1 <= row0 + 8) ? expq(S[nt][3]) : 0.f;
                l0 += p0 + p1;
                l1 += p2 + p3;
                __nv_bfloat16 h0 = __float2bfloat16(p0), h1 = __float2bfloat16(p1);
                __nv_bfloat16 h2 = __float2bfloat16(p2), h3 = __float2bfloat16(p3);
                float r0 = p0 - __bfloat162float(h0), r1 = p1 - __bfloat162float(h1);
                float r2 = p2 - __bfloat162float(h2), r3 = p3 - __bfloat162float(h3);
                int ks2 = nt >> 1, off = (nt & 1) * 2;
                pah[ks2][off]     = pack2h(h0, h1);
                pah[ks2][off + 1] = pack2h(h2, h3);
                pal[ks2][off]     = pack2f(r0, r1);
                pal[ks2][off + 1] = pack2f(r2, r3);
            }
        }

        #pragma unroll
        for (int ks2 = 0; ks2 < 4; ks2++) {
            uint32_t fvh[4][4], fvl[4][4];
            #pragma unroll
            for (int n2 = 0; n2 < 4; n2++) {
                uint32_t a = stV + (n2 * 16 + bRow) * FP + bK16 + ks2 * 32;
                ldsm4(fvh[n2], a);
                ldsm4(fvl[n2], a + 9216);
            }
            #pragma unroll
            for (int nt = 0; nt < 8; nt++) {
                mma16816(o[nt], pah[ks2], fvh[nt >> 1][(nt & 1) * 2], fvh[nt >> 1][(nt & 1) * 2 + 1]);
                mma16816(o[nt], pah[ks2], fvl[nt >> 1][(nt & 1) * 2], fvl[nt >> 1][(nt & 1) * 2 + 1]);
                mma16816(o[nt], pal[ks2], fvh[nt >> 1][(nt & 1) * 2], fvh[nt >> 1][(nt & 1) * 2 + 1]);
            }
        }
    }

    l0 += __shfl_xor_sync(0xFFFFFFFFu, l0, 1);
    l0 += __shfl_xor_sync(0xFFFFFFFFu, l0, 2);
    l1 += __shfl_xor_sync(0xFFFFFFFFu, l1, 1);
    l1 += __shfl_xor_sync(0xFFFFFFFFu, l1, 2);
    float inv0 = 1.0f / l0, inv1 = 1.0f / l1;

    int b = bh >> 4, h = bh & 15;
    int srow = qt * 128 + wid * 16 + g;
    #pragma unroll
    for (int nt = 0; nt < 8; nt++) {
        int d = nt * 8 + t2;
        size_t o0 = (size_t)(b * SEQ + srow) * DIM + h * DH + d;
        size_t o1 = (size_t)(b * SEQ + srow + 8) * DIM + h * DH + d;
        uint32_t hi, lo;
        split2(o[nt][0] * inv0, o[nt][1] * inv0, hi, lo);
        *(uint32_t*)&Oh[o0] = hi;  *(uint32_t*)&Ol[o0] = lo;
        split2(o[nt][2] * inv1, o[nt][3] * inv1, hi, lo);
        *(uint32_t*)&Oh[o1] = hi;  *(uint32_t*)&Ol[o1] = lo;
    }
}

// ===========================================================================
// Launch
// ===========================================================================
extern "C" void kernel_launch(void* const* d_in, const int* in_sizes, int n_in,
                              void* d_out, int out_size)
{
    (void)in_sizes; (void)n_in; (void)out_size;
    const float* x  = (const float*)d_in[0];
    const float* ns = (const float*)d_in[1];
    const float* Wq = (const float*)d_in[2];
    const float* Wk = (const float*)d_in[3];
    const float* Wv = (const float*)d_in[4];
    const float* Wo = (const float*)d_in[5];
    float* out = (float*)d_out;

    float *qkv, *sinT, *cosT;
    __nv_bfloat16 *ah, *al, *th, *tl, *qhp, *qlp, *khp, *klp, *vth, *vtl;
    cudaGetSymbolAddress((void**)&qkv, g_qkv);
    cudaGetSymbolAddress((void**)&sinT, g_sinT);
    cudaGetSymbolAddress((void**)&cosT, g_cosT);
    cudaGetSymbolAddress((void**)&ah, g_ah);
    cudaGetSymbolAddress((void**)&al, g_al);
    cudaGetSymbolAddress((void**)&th, g_th);
    cudaGetSymbolAddress((void**)&tl, g_tl);
    cudaGetSymbolAddress((void**)&qhp, g_qh);
    cudaGetSymbolAddress((void**)&qlp, g_ql);
    cudaGetSymbolAddress((void**)&khp, g_kh);
    cudaGetSymbolAddress((void**)&klp, g_kl);
    cudaGetSymbolAddress((void**)&vth, g_vth);
    cudaGetSymbolAddress((void**)&vtl, g_vtl);

    cudaFuncSetAttribute(mma_gemm_kernel,
                         cudaFuncAttributeMaxDynamicSharedMemorySize, GEMM_SMEM);
    cudaFuncSetAttribute(flash_mma_kernel,
                         cudaFuncAttributeMaxDynamicSharedMemorySize, FL_SMEM);

    prologue_kernel<<<dim3(DIM / 32, DIM / 32, 9), 256>>>(
        x, ns, Wq, Wk, Wv, Wo, th, tl, sinT, cosT, ah, al);

    mma_gemm_kernel<<<dim3(3 * (DIM / 128), ROWS / 256), 256, GEMM_SMEM>>>(
        ah, al, th, tl, qkv);

    qkv_prep_kernel<<<4096 + 4096, 256>>>(
        qkv, sinT, cosT, qhp, qlp, khp, klp, vth, vtl);

    flash_mma_kernel<<<dim3(SEQ / 128, BATCH * NH), 256, FL_SMEM>>>(
        qhp, qlp, khp, klp, vth, vtl, ah, al);

    mma_gemm_kernel<<<dim3(DIM / 128, ROWS / 256), 256, GEMM_SMEM>>>(
        ah, al, th + (size_t)3 * DIM * DIM, tl + (size_t)3 * DIM * DIM, out);
}

// round 13
// speedup vs baseline: 1.0131x; 1.0131x over previous
#include <cuda_runtime.h>
#include <cuda_bf16.h>
#include <stdint.h>
#include <math.h>

#define BATCH 2
#define SEQ   2048
#define DIM   1024
#define ROWS  (BATCH*SEQ)   // 4096
#define NH    16
#define DH    64

// Scratch (allocation-free rule: __device__ globals)
__device__ float g_qkv[3*ROWS*DIM];          // Q,K,V fp32 outputs
__device__ float g_sinT[SEQ*32];             // RoPE tables [pos][i]
__device__ float g_cosT[SEQ*32];
__device__ __nv_bfloat16 g_ah[ROWS*DIM];     // x_norm split hi; later attn-out hi
__device__ __nv_bfloat16 g_al[ROWS*DIM];     // x_norm split lo; later attn-out lo
__device__ __nv_bfloat16 g_th[4*DIM*DIM];    // W^T split hi [4][N][K] (q,k,v,o)
__device__ __nv_bfloat16 g_tl[4*DIM*DIM];    // W^T split lo
// attention operands, head-contiguous layouts
__device__ __nv_bfloat16 g_qh[ROWS*DIM];     // Q hi (roped) [bh][s][d]
__device__ __nv_bfloat16 g_ql[ROWS*DIM];
__device__ __nv_bfloat16 g_kh[ROWS*DIM];     // K hi (roped) [bh][s][d]
__device__ __nv_bfloat16 g_kl[ROWS*DIM];
__device__ __nv_bfloat16 g_vth[ROWS*DIM];    // V^T hi [bh][d][s]
__device__ __nv_bfloat16 g_vtl[ROWS*DIM];

// ===========================================================================
// Portable (compute_103-safe) PTX helpers: mma.sync / ldmatrix / cp.async
// ===========================================================================
__device__ __forceinline__ uint32_t smem_u32(const void* p) {
    uint32_t a;
    asm("{ .reg .u64 t; cvta.to.shared.u64 t, %1; cvt.u32.u64 %0, t; }"
        : "=r"(a) : "l"(p));
    return a;
}
__device__ __forceinline__ void cp_async16(uint32_t saddr, const void* gaddr) {
    asm volatile("cp.async.cg.shared.global [%0], [%1], 16;"
                 :: "r"(saddr), "l"(gaddr));
}
__device__ __forceinline__ void cp_commit() {
    asm volatile("cp.async.commit_group;" ::: "memory");
}
__device__ __forceinline__ void ldsm4(uint32_t* r, uint32_t addr) {
    asm volatile("ldmatrix.sync.aligned.m8n8.x4.shared.b16 {%0,%1,%2,%3}, [%4];"
                 : "=r"(r[0]), "=r"(r[1]), "=r"(r[2]), "=r"(r[3]) : "r"(addr));
}
__device__ __forceinline__ void mma16816(float* c, const uint32_t* a,
                                         uint32_t b0, uint32_t b1) {
    asm volatile(
        "mma.sync.aligned.m16n8k16.row.col.f32.bf16.bf16.f32 "
        "{%0,%1,%2,%3}, {%4,%5,%6,%7}, {%8,%9}, {%0,%1,%2,%3};"
        : "+f"(c[0]), "+f"(c[1]), "+f"(c[2]), "+f"(c[3])
        : "r"(a[0]), "r"(a[1]), "r"(a[2]), "r"(a[3]), "r"(b0), "r"(b1));
}
__device__ __forceinline__ uint32_t pack2h(__nv_bfloat16 a, __nv_bfloat16 b) {
    __nv_bfloat162 t = __halves2bfloat162(a, b);
    return *reinterpret_cast<uint32_t*>(&t);
}
__device__ __forceinline__ uint32_t pack2f(float a, float b) {
    __nv_bfloat162 t = __floats2bfloat162_rn(a, b);
    return *reinterpret_cast<uint32_t*>(&t);
}
__device__ __forceinline__ void split2(float a, float b, uint32_t& hi, uint32_t& lo) {
    __nv_bfloat16 ha = __float2bfloat16(a), hb = __float2bfloat16(b);
    hi = pack2h(ha, hb);
    lo = pack2f(a - __bfloat162float(ha), b - __bfloat162float(hb));
}
// exp(x*0.125) as a single FMUL + MUFU: ex2(x * 0.125*log2(e))
__device__ __forceinline__ float expq(float x) {
    float y;
    asm("ex2.approx.ftz.f32 %0, %1;" : "=f"(y) : "f"(x * 0.1803368801111244f));
    return y;
}

// ===========================================================================
// MERGED prologue: one launch does everything independent of the QKV GEMM.
//   z in [0,4): transpose+split weight z
//   z == 4   : RoPE sin/cos table
//   z in [5,9): RMSNorm + bf16 split, rows (z-5)*1024 + by*32 + bx
// ===========================================================================
__global__ __launch_bounds__(256) void prologue_kernel(
    const float* __restrict__ x, const float* __restrict__ sc,
    const float* __restrict__ W0, const float* __restrict__ W1,
    const float* __restrict__ W2, const float* __restrict__ W3,
    __nv_bfloat16* __restrict__ Th, __nv_bfloat16* __restrict__ Tl,
    float* __restrict__ sinT, float* __restrict__ cosT,
    __nv_bfloat16* __restrict__ ah, __nv_bfloat16* __restrict__ al)
{
    __shared__ float tile[32][33];
    __shared__ float red[256];
    int z = blockIdx.z;

    if (z == 4) {
        int idx = (blockIdx.y * 32 + blockIdx.x) * 256 + threadIdx.x;
        if (idx < SEQ * 32) {
            int pos = idx >> 5, i = idx & 31;
            float e = (2.0f * (float)i) / (float)DH;
            float theta = exp2f(-e * 19.931568569324174f);   // 1e6^-e
            float ang = (float)pos * theta;
            sinT[idx] = sinf(ang);
            cosT[idx] = cosf(ang);
        }
        return;
    }

    if (z >= 5) {
        int row = (z - 5) * 1024 + blockIdx.y * 32 + blockIdx.x;
        const float* xr = x + (size_t)row * DIM;
        float v[4];
        float ss = 0.f;
        #pragma unroll
        for (int j = 0; j < 4; j++) {
            v[j] = xr[threadIdx.x + j * 256];
            ss = fmaf(v[j], v[j], ss);
        }
        red[threadIdx.x] = ss;
        __syncthreads();
        #pragma unroll
        for (int s = 128; s > 0; s >>= 1) {
            if (threadIdx.x < s) red[threadIdx.x] += red[threadIdx.x + s];
            __syncthreads();
        }
        float r = rsqrtf(red[0] * (1.0f / DIM) + 1e-6f);
        #pragma unroll
        for (int j = 0; j < 4; j++) {
            int i = threadIdx.x + j * 256;
            float y = v[j] * r * sc[i];
            __nv_bfloat16 h = __float2bfloat16(y);
            ah[(size_t)row * DIM + i] = h;
            al[(size_t)row * DIM + i] = __float2bfloat16(y - __bfloat162float(h));
        }
        return;
    }

    const float* W = (z == 0) ? W0 : (z == 1) ? W1 : (z == 2) ? W2 : W3;
    __nv_bfloat16* th = Th + (size_t)z * DIM * DIM;
    __nv_bfloat16* tl = Tl + (size_t)z * DIM * DIM;

    int k0 = blockIdx.y * 32, n0 = blockIdx.x * 32;
    int tx = threadIdx.x & 31, ty = threadIdx.x >> 5;   // 32 x 8
    #pragma unroll
    for (int i = 0; i < 32; i += 8)
        tile[ty + i][tx] = W[(size_t)(k0 + ty + i) * DIM + n0 + tx];
    __syncthreads();
    #pragma unroll
    for (int i = 0; i < 32; i += 8) {
        float v = tile[tx][ty + i];    // = W[k0+tx][n0+ty+i]
        __nv_bfloat16 h = __float2bfloat16(v);
        float r = v - __bfloat162float(h);
        size_t o = (size_t)(n0 + ty + i) * DIM + k0 + tx;
        th[o] = h;
        tl[o] = __float2bfloat16(r);
    }
}

// ===========================================================================
// bf16-split GEMM via mma.sync. 3-stage cp.async pipeline (validated R10).
// ===========================================================================
#define A_TILE_B 20480             // 256 rows x 80 bytes
#define B_TILE_B 10240             // 128 rows x 80 bytes
#define STG_B    (2*A_TILE_B + 2*B_TILE_B)   // 61440
#define GEMM_SMEM (3*STG_B)                   // 184320 (3 stages)

__global__ __launch_bounds__(256) void mma_gemm_kernel(
    const __nv_bfloat16* __restrict__ Ah, const __nv_bfloat16* __restrict__ Al,
    const __nv_bfloat16* __restrict__ BhBase, const __nv_bfloat16* __restrict__ BlBase,
    float* __restrict__ CBase)
{
    extern __shared__ char smem[];
    uint32_t sb = smem_u32(smem);

    const int tid  = threadIdx.x;
    const int lane = tid & 31;
    const int wid  = tid >> 5;
    const int warp_m = wid & 3;
    const int warp_n = wid >> 2;
    const int which = blockIdx.x >> 3;               // weight index
    const int bm = blockIdx.y * 256;
    const int bn = (blockIdx.x & 7) * 128;

    const __nv_bfloat16* Bh = BhBase + (size_t)which * DIM * DIM;
    const __nv_bfloat16* Bl = BlBase + (size_t)which * DIM * DIM;
    float* C = CBase + (size_t)which * ROWS * DIM;

    float acc[4][8][4];
    #pragma unroll
    for (int i = 0; i < 4; i++)
        #pragma unroll
        for (int j = 0; j < 8; j++)
            #pragma unroll
            for (int q = 0; q < 4; q++) acc[i][j][q] = 0.f;

    auto load_stage = [&](int kt, int s) {
        const __nv_bfloat16* asrc[2] = {Ah, Al};
        #pragma unroll
        for (int t = 0; t < 2; t++) {
            #pragma unroll
            for (int i = 0; i < 4; i++) {
                int chunk = tid + i * 256;         // 0..1023
                int row = chunk >> 2, c = chunk & 3;
                cp_async16(sb + s * STG_B + t * A_TILE_B + row * 80 + c * 16,
                           asrc[t] + (size_t)(bm + row) * DIM + kt * 32 + c * 8);
            }
        }
        const __nv_bfloat16* bsrc[2] = {Bh, Bl};
        #pragma unroll
        for (int t = 0; t < 2; t++) {
            #pragma unroll
            for (int i = 0; i < 2; i++) {
                int chunk = tid + i * 256;         // 0..511
                int row = chunk >> 2, c = chunk & 3;
                cp_async16(sb + s * STG_B + 2 * A_TILE_B + t * B_TILE_B + row * 80 + c * 16,
                           bsrc[t] + (size_t)(bn + row) * DIM + kt * 32 + c * 8);
            }
        }
        cp_commit();
    };

    load_stage(0, 0);
    load_stage(1, 1);

    const int aRow = lane & 15;
    const int aK16 = (lane >> 4) * 16;
    const int bRow = (lane & 7) + ((lane >> 4) << 3);
    const int bK16 = ((lane >> 3) & 1) * 16;

    int sNext = 2;   // stage index for kt+2
    for (int kt = 0; kt < 32; kt++) {
        if (kt < 31) asm volatile("cp.async.wait_group 1;" ::: "memory");
        else         asm volatile("cp.async.wait_group 0;" ::: "memory");
        __syncthreads();

        if (kt + 2 < 32) load_stage(kt + 2, sNext);

        int sCur = sNext + 1; if (sCur >= 3) sCur -= 3;   // == kt % 3
        uint32_t st  = sb + sCur * STG_B;
        uint32_t aHb = st + (warp_m * 64 + aRow) * 80 + aK16;
        uint32_t aLb = aHb + A_TILE_B;
        uint32_t bHb = st + 2 * A_TILE_B + (warp_n * 64 + bRow) * 80 + bK16;
        uint32_t bLb = bHb + B_TILE_B;
        sNext = sCur;

        #pragma unroll
        for (int ks = 0; ks < 2; ks++) {
            uint32_t koff = ks * 32;
            uint32_t fah[4][4], fal[4][4], fb[4][4];
            #pragma unroll
            for (int mt = 0; mt < 4; mt++) {
                ldsm4(fah[mt], aHb + mt * 1280 + koff);
                ldsm4(fal[mt], aLb + mt * 1280 + koff);
            }
            #pragma unroll
            for (int n2 = 0; n2 < 4; n2++)
                ldsm4(fb[n2], bHb + n2 * 1280 + koff);
            #pragma unroll
            for (int mt = 0; mt < 4; mt++)
                #pragma unroll
                for (int nt = 0; nt < 8; nt++)
                    mma16816(acc[mt][nt], fah[mt],
                             fb[nt >> 1][(nt & 1) * 2], fb[nt >> 1][(nt & 1) * 2 + 1]);
            #pragma unroll
            for (int mt = 0; mt < 4; mt++)
                #pragma unroll
                for (int nt = 0; nt < 8; nt++)
                    mma16816(acc[mt][nt], fal[mt],
                             fb[nt >> 1][(nt & 1) * 2], fb[nt >> 1][(nt & 1) * 2 + 1]);
            #pragma unroll
            for (int n2 = 0; n2 < 4; n2++)
                ldsm4(fb[n2], bLb + n2 * 1280 + koff);
            #pragma unroll
            for (int mt = 0; mt < 4; mt++)
                #pragma unroll
                for (int nt = 0; nt < 8; nt++)
                    mma16816(acc[mt][nt], fah[mt],
                             fb[nt >> 1][(nt & 1) * 2], fb[nt >> 1][(nt & 1) * 2 + 1]);
        }
    }

    const int g = lane >> 2, t2 = (lane & 3) * 2;
    #pragma unroll
    for (int mt = 0; mt < 4; mt++) {
        #pragma unroll
        for (int nt = 0; nt < 8; nt++) {
            int row = bm + warp_m * 64 + mt * 16 + g;
            int col = bn + warp_n * 64 + nt * 8 + t2;
            *(float2*)&C[(size_t)row * DIM + col] =
                make_float2(acc[mt][nt][0], acc[mt][nt][1]);
            *(float2*)&C[(size_t)(row + 8) * DIM + col] =
                make_float2(acc[mt][nt][2], acc[mt][nt][3]);
        }
    }
}

// ===========================================================================
// Merged RoPE-split (float4 vectorized) + V transpose-split (4B stores).
// ===========================================================================
__global__ __launch_bounds__(256) void qkv_prep_kernel(
    const float* __restrict__ qkv,
    const float* __restrict__ sinT, const float* __restrict__ cosT,
    __nv_bfloat16* __restrict__ Qh, __nv_bfloat16* __restrict__ Ql,
    __nv_bfloat16* __restrict__ Kh, __nv_bfloat16* __restrict__ Kl,
    __nv_bfloat16* __restrict__ Vth, __nv_bfloat16* __restrict__ Vtl)
{
    __shared__ float tile[32][33];
    int bid = blockIdx.x;

    if (bid < 4096) {
        int idx = bid * 256 + threadIdx.x;     // 2^20 total
        int which = idx >> 19;                 // 0=q, 1=k
        int r   = idx & ((1 << 19) - 1);
        int row = r >> 7;                      // 128 = 16 heads * 8
        int rem = r & 127;
        int head = rem >> 3;
        int i4   = (rem & 7) * 4;

        const float* src = qkv + (size_t)which * ROWS * DIM
                               + (size_t)row * DIM + head * DH;
        int pos = row & (SEQ - 1);

        float4 sn = *(const float4*)&sinT[pos * 32 + i4];
        float4 cs = *(const float4*)&cosT[pos * 32 + i4];
        float4 x1 = *(const float4*)&src[i4];
        float4 x2 = *(const float4*)&src[i4 + 32];

        float y1a = x1.x * cs.x - x2.x * sn.x, y2a = x1.x * sn.x + x2.x * cs.x;
        float y1b = x1.y * cs.y - x2.y * sn.y, y2b = x1.y * sn.y + x2.y * cs.y;
        float y1c = x1.z * cs.z - x2.z * sn.z, y2c = x1.z * sn.z + x2.z * cs.z;
        float y1d = x1.w * cs.w - x2.w * sn.w, y2d = x1.w * sn.w + x2.w * cs.w;

        int b = row >> 11, s = row & (SEQ - 1);
        size_t o = ((size_t)(b * NH + head) * SEQ + s) * DH + i4;
        __nv_bfloat16* H = which ? Kh : Qh;
        __nv_bfloat16* L = which ? Kl : Ql;
        uint32_t h0, l0, h1, l1;
        split2(y1a, y1b, h0, l0);
        split2(y1c, y1d, h1, l1);
        *(uint2*)&H[o] = make_uint2(h0, h1);
        *(uint2*)&L[o] = make_uint2(l0, l1);
        split2(y2a, y2b, h0, l0);
        split2(y2c, y2d, h1, l1);
        *(uint2*)&H[o + 32] = make_uint2(h0, h1);
        *(uint2*)&L[o + 32] = make_uint2(l0, l1);
    } else {
        int b2 = bid - 4096;                 // [0, 4096)
        int s0 = (b2 & 63) * 32;
        int d0 = ((b2 >> 6) & 1) * 32;
        int bh = b2 >> 7;
        int b = bh >> 4, h = bh & 15;
        const float* v = qkv + (size_t)2 * ROWS * DIM;
        int tx = threadIdx.x & 31, ty = threadIdx.x >> 5;
        #pragma unroll
        for (int i = 0; i < 32; i += 8)
            tile[ty + i][tx] = v[(size_t)(b * SEQ + s0 + ty + i) * DIM + h * DH + d0 + tx];
        __syncthreads();
        int sx = threadIdx.x & 15;
        int dy = threadIdx.x >> 4;
        #pragma unroll
        for (int dd = 0; dd < 32; dd += 16) {
            int d = dy + dd;
            float va = tile[sx * 2][d];
            float vb = tile[sx * 2 + 1][d];
            uint32_t hi, lo;
            split2(va, vb, hi, lo);
            size_t o = ((size_t)(bh * DH + d0 + d)) * SEQ + s0 + sx * 2;
            *(uint32_t*)&Vth[o] = hi;
            *(uint32_t*)&Vtl[o] = lo;
        }
    }
}

// ===========================================================================
// Flash attention via mma.sync, split-bf16.
// 2-stage KV ring (110.5 KB smem) + 128-reg body => 2 CTAs/SM.
// ===========================================================================
#define FP      144                 // smem row pitch (bytes)
#define FQ_OFF  0                   // Qh @0, Ql @18432 (128 rows x 144)
#define FK_OFF  36864               // + stage*18432; Kh +0, Kl +9216
#define FV_OFF  73728               // + stage*18432; Vh +0, Vl +9216
#define FL_SMEM 110592              // 36864 + 2*18432 + 2*18432

__global__ __launch_bounds__(256, 2) void flash_mma_kernel(
    const __nv_bfloat16* __restrict__ Qh_, const __nv_bfloat16* __restrict__ Ql_,
    const __nv_bfloat16* __restrict__ Kh_, const __nv_bfloat16* __restrict__ Kl_,
    const __nv_bfloat16* __restrict__ Vth_, const __nv_bfloat16* __restrict__ Vtl_,
    __nv_bfloat16* __restrict__ Oh, __nv_bfloat16* __restrict__ Ol)
{
    extern __shared__ char smem[];
    uint32_t sb = smem_u32(smem);
    const int tid = threadIdx.x, lane = tid & 31, wid = tid >> 5;
    const int bh = blockIdx.y;
    const int qt = (gridDim.x - 1) - blockIdx.x;   // heavy tiles first
    const int nkt = 2 * (qt + 1);                  // 64-key chunks
    const size_t qkoff = (size_t)bh * SEQ * DH;
    const size_t voff  = (size_t)bh * DH * SEQ;

    // Q tile load (once)
    {
        const __nv_bfloat16* qs[2] = {Qh_ + qkoff, Ql_ + qkoff};
        #pragma unroll
        for (int i = 0; i < 8; i++) {
            int idx = tid + i * 256;           // 0..2047
            int t = idx >> 10, rem = idx & 1023;
            int row = rem >> 3, c = rem & 7;
            cp_async16(sb + FQ_OFF + t * 18432 + row * FP + c * 16,
                       qs[t] + (size_t)(qt * 128 + row) * DH + c * 8);
        }
        cp_commit();
    }

    auto load_kv = [&](int kt, int s) {
        int k0 = kt * 64;
        const __nv_bfloat16* ks_[2] = {Kh_ + qkoff, Kl_ + qkoff};
        const __nv_bfloat16* vs_[2] = {Vth_ + voff, Vtl_ + voff};
        #pragma unroll
        for (int i = 0; i < 4; i++) {
            int idx = tid + i * 256;           // 0..1023
            int t = idx >> 9, rem = idx & 511;
            int row = rem >> 3, c = rem & 7;
            cp_async16(sb + FK_OFF + s * 18432 + t * 9216 + row * FP + c * 16,
                       ks_[t] + (size_t)(k0 + row) * DH + c * 8);
        }
        #pragma unroll
        for (int i = 0; i < 4; i++) {
            int idx = tid + i * 256;
            int t = idx >> 9, rem = idx & 511;
            int row = rem >> 3, c = rem & 7;   // row = dh index, c = key chunk
            cp_async16(sb + FV_OFF + s * 18432 + t * 9216 + row * FP + c * 16,
                       vs_[t] + (size_t)row * SEQ + k0 + c * 8);
        }
        cp_commit();
    };
    load_kv(0, 0);
    load_kv(1, 1);

    const int g = lane >> 2, t2 = (lane & 3) * 2;
    const int aRow = lane & 15, aK16 = (lane >> 4) * 16;
    const int bRow = (lane & 7) + ((lane >> 4) << 3);
    const int bK16 = ((lane >> 3) & 1) * 16;

    asm volatile("cp.async.wait_group 2;" ::: "memory");
    __syncthreads();

    uint32_t qh[4][4], ql[4][4];
    {
        uint32_t base = sb + FQ_OFF + (wid * 16 + aRow) * FP + aK16;
        #pragma unroll
        for (int ks = 0; ks < 4; ks++) {
            ldsm4(qh[ks], base + ks * 32);
            ldsm4(ql[ks], base + 18432 + ks * 32);
        }
    }

    float o[8][4];
    #pragma unroll
    for (int nt = 0; nt < 8; nt++)
        #pragma unroll
        for (int j = 0; j < 4; j++) o[nt][j] = 0.f;
    float l0 = 0.f, l1 = 0.f;
    const int row0 = qt * 128 + wid * 16 + g;
    const int rowWarpMin = qt * 128 + wid * 16;   // warp-uniform

    for (int kt = 0; kt < nkt; kt++) {
        if (kt < nkt - 1) asm volatile("cp.async.wait_group 1;" ::: "memory");
        else              asm volatile("cp.async.wait_group 0;" ::: "memory");
        __syncthreads();

        uint32_t stK = sb + FK_OFF + (kt & 1) * 18432;
        uint32_t stV = sb + FV_OFF + (kt & 1) * 18432;

        float S[8][4];
        #pragma unroll
        for (int nt = 0; nt < 8; nt++)
            #pragma unroll
            for (int j = 0; j < 4; j++) S[nt][j] = 0.f;

        #pragma unroll
        for (int ks = 0; ks < 4; ks++) {
            uint32_t fkh[4][4], fkl[4][4];
            #pragma unroll
            for (int n2 = 0; n2 < 4; n2++) {
                uint32_t a = stK + (n2 * 16 + bRow) * FP + bK16 + ks * 32;
                ldsm4(fkh[n2], a);
                ldsm4(fkl[n2], a + 9216);
            }
            #pragma unroll
            for (int nt = 0; nt < 8; nt++) {
                mma16816(S[nt], qh[ks], fkh[nt >> 1][(nt & 1) * 2], fkh[nt >> 1][(nt & 1) * 2 + 1]);
                mma16816(S[nt], qh[ks], fkl[nt >> 1][(nt & 1) * 2], fkl[nt >> 1][(nt & 1) * 2 + 1]);
                mma16816(S[nt], ql[ks], fkh[nt >> 1][(nt & 1) * 2], fkh[nt >> 1][(nt & 1) * 2 + 1]);
            }
        }

        // ---- softmax + pack P; warp-uniform fast path ----
        uint32_t pah[4][4], pal[4][4];
        int k0 = kt * 64;
        if (k0 + 63 <= rowWarpMin) {
            #pragma unroll
            for (int nt = 0; nt < 8; nt++) {
                float p0 = expq(S[nt][0]);
                float p1 = expq(S[nt][1]);
                float p2 = expq(S[nt][2]);
                float p3 = expq(S[nt][3]);
                l0 += p0 + p1;
                l1 += p2 + p3;
                __nv_bfloat16 h0 = __float2bfloat16(p0), h1 = __float2bfloat16(p1);
                __nv_bfloat16 h2 = __float2bfloat16(p2), h3 = __float2bfloat16(p3);
                float r0 = p0 - __bfloat162float(h0), r1 = p1 - __bfloat162float(h1);
                float r2 = p2 - __bfloat162float(h2), r3 = p3 - __bfloat162float(h3);
                int ks2 = nt >> 1, off = (nt & 1) * 2;
                pah[ks2][off]     = pack2h(h0, h1);
                pah[ks2][off + 1] = pack2h(h2, h3);
                pal[ks2][off]     = pack2f(r0, r1);
                pal[ks2][off + 1] = pack2f(r2, r3);
            }
        } else {
            #pragma unroll
            for (int nt = 0; nt < 8; nt++) {
                int col = k0 + nt * 8 + t2;
                float p0 = (col     <= row0)     ? expq(S[nt][0]) : 0.f;
                float p1 = (col + 1 <= row0)     ? expq(S[nt][1]) : 0.f;
                float p2 = (col     <= row0 + 8) ? expq(S[nt][2]) : 0.f;
                float p3 = (col + 1 <= row0 + 8) ? expq(S[nt][3]) : 0.f;
                l0 += p0 + p1;
                l1 += p2 + p3;
                __nv_bfloat16 h0 = __float2bfloat16(p0), h1 = __float2bfloat16(p1);
                __nv_bfloat16 h2 = __float2bfloat16(p2), h3 = __float2bfloat16(p3);
                float r0 = p0 - __bfloat162float(h0), r1 = p1 - __bfloat162float(h1);
                float r2 = p2 - __bfloat162float(h2), r3 = p3 - __bfloat162float(h3);
                int ks2 = nt >> 1, off = (nt & 1) * 2;
                pah[ks2][off]     = pack2h(h0, h1);
                pah[ks2][off + 1] = pack2h(h2, h3);
                pal[ks2][off]     = pack2f(r0, r1);
                pal[ks2][off + 1] = pack2f(r2, r3);
            }
        }

        #pragma unroll
        for (int ks2 = 0; ks2 < 4; ks2++) {
            uint32_t fvh[4][4], fvl[4][4];
            #pragma unroll
            for (int n2 = 0; n2 < 4; n2++) {
                uint32_t a = stV + (n2 * 16 + bRow) * FP + bK16 + ks2 * 32;
                ldsm4(fvh[n2], a);
                ldsm4(fvl[n2], a + 9216);
            }
            #pragma unroll
            for (int nt = 0; nt < 8; nt++) {
                mma16816(o[nt], pah[ks2], fvh[nt >> 1][(nt & 1) * 2], fvh[nt >> 1][(nt & 1) * 2 + 1]);
                mma16816(o[nt], pah[ks2], fvl[nt >> 1][(nt & 1) * 2], fvl[nt >> 1][(nt & 1) * 2 + 1]);
                mma16816(o[nt], pal[ks2], fvh[nt >> 1][(nt & 1) * 2], fvh[nt >> 1][(nt & 1) * 2 + 1]);
            }
        }

        __syncthreads();
        if (kt + 2 < nkt) load_kv(kt + 2, kt & 1);
    }

    l0 += __shfl_xor_sync(0xFFFFFFFFu, l0, 1);
    l0 += __shfl_xor_sync(0xFFFFFFFFu, l0, 2);
    l1 += __shfl_xor_sync(0xFFFFFFFFu, l1, 1);
    l1 += __shfl_xor_sync(0xFFFFFFFFu, l1, 2);
    float inv0 = 1.0f / l0, inv1 = 1.0f / l1;

    int b = bh >> 4, h = bh & 15;
    int srow = qt * 128 + wid * 16 + g;
    #pragma unroll
    for (int nt = 0; nt < 8; nt++) {
        int d = nt * 8 + t2;
        size_t o0 = (size_t)(b * SEQ + srow) * DIM + h * DH + d;
        size_t o1 = (size_t)(b * SEQ + srow + 8) * DIM + h * DH + d;
        uint32_t hi, lo;
        split2(o[nt][0] * inv0, o[nt][1] * inv0, hi, lo);
        *(uint32_t*)&Oh[o0] = hi;  *(uint32_t*)&Ol[o0] = lo;
        split2(o[nt][2] * inv1, o[nt][3] * inv1, hi, lo);
        *(uint32_t*)&Oh[o1] = hi;  *(uint32_t*)&Ol[o1] = lo;
    }
}

// ===========================================================================
// Launch
// ===========================================================================
extern "C" void kernel_launch(void* const* d_in, const int* in_sizes, int n_in,
                              void* d_out, int out_size)
{
    (void)in_sizes; (void)n_in; (void)out_size;
    const float* x  = (const float*)d_in[0];
    const float* ns = (const float*)d_in[1];
    const float* Wq = (const float*)d_in[2];
    const float* Wk = (const float*)d_in[3];
    const float* Wv = (const float*)d_in[4];
    const float* Wo = (const float*)d_in[5];
    float* out = (float*)d_out;

    float *qkv, *sinT, *cosT;
    __nv_bfloat16 *ah, *al, *th, *tl, *qhp, *qlp, *khp, *klp, *vth, *vtl;
    cudaGetSymbolAddress((void**)&qkv, g_qkv);
    cudaGetSymbolAddress((void**)&sinT, g_sinT);
    cudaGetSymbolAddress((void**)&cosT, g_cosT);
    cudaGetSymbolAddress((void**)&ah, g_ah);
    cudaGetSymbolAddress((void**)&al, g_al);
    cudaGetSymbolAddress((void**)&th, g_th);
    cudaGetSymbolAddress((void**)&tl, g_tl);
    cudaGetSymbolAddress((void**)&qhp, g_qh);
    cudaGetSymbolAddress((void**)&qlp, g_ql);
    cudaGetSymbolAddress((void**)&khp, g_kh);
    cudaGetSymbolAddress((void**)&klp, g_kl);
    cudaGetSymbolAddress((void**)&vth, g_vth);
    cudaGetSymbolAddress((void**)&vtl, g_vtl);

    cudaFuncSetAttribute(mma_gemm_kernel,
                         cudaFuncAttributeMaxDynamicSharedMemorySize, GEMM_SMEM);
    cudaFuncSetAttribute(flash_mma_kernel,
                         cudaFuncAttributeMaxDynamicSharedMemorySize, FL_SMEM);

    prologue_kernel<<<dim3(DIM / 32, DIM / 32, 9), 256>>>(
        x, ns, Wq, Wk, Wv, Wo, th, tl, sinT, cosT, ah, al);

    mma_gemm_kernel<<<dim3(3 * (DIM / 128), ROWS / 256), 256, GEMM_SMEM>>>(
        ah, al, th, tl, qkv);

    qkv_prep_kernel<<<4096 + 4096, 256>>>(
        qkv, sinT, cosT, qhp, qlp, khp, klp, vth, vtl);

    flash_mma_kernel<<<dim3(SEQ / 128, BATCH * NH), 256, FL_SMEM>>>(
        qhp, qlp, khp, klp, vth, vtl, ah, al);

    mma_gemm_kernel<<<dim3(DIM / 128, ROWS / 256), 256, GEMM_SMEM>>>(
        ah, al, th + (size_t)3 * DIM * DIM, tl + (size_t)3 * DIM * DIM, out);
}

// round 14
// speedup vs baseline: 1.0154x; 1.0023x over previous
#include <cuda_runtime.h>
#include <cuda_bf16.h>
#include <stdint.h>
#include <math.h>

#define BATCH 2
#define SEQ   2048
#define DIM   1024
#define ROWS  (BATCH*SEQ)   // 4096
#define NH    16
#define DH    64

// Scratch (allocation-free rule: __device__ globals)
__device__ float g_qkv[3*ROWS*DIM];          // Q,K,V fp32 outputs
__device__ float g_sinT[SEQ*32];             // RoPE tables [pos][i]
__device__ float g_cosT[SEQ*32];
__device__ __nv_bfloat16 g_ah[ROWS*DIM];     // x_norm split hi; later attn-out hi
__device__ __nv_bfloat16 g_al[ROWS*DIM];     // x_norm split lo; later attn-out lo
__device__ __nv_bfloat16 g_th[4*DIM*DIM];    // W^T split hi [4][N][K] (q,k,v,o)
__device__ __nv_bfloat16 g_tl[4*DIM*DIM];    // W^T split lo
// attention operands, head-contiguous layouts
__device__ __nv_bfloat16 g_qh[ROWS*DIM];     // Q hi (roped) [bh][s][d]
__device__ __nv_bfloat16 g_ql[ROWS*DIM];
__device__ __nv_bfloat16 g_kh[ROWS*DIM];     // K hi (roped) [bh][s][d]
__device__ __nv_bfloat16 g_kl[ROWS*DIM];
__device__ __nv_bfloat16 g_vth[ROWS*DIM];    // V^T hi [bh][d][s]
__device__ __nv_bfloat16 g_vtl[ROWS*DIM];

// ===========================================================================
// Portable (compute_103-safe) PTX helpers: mma.sync / ldmatrix / cp.async
// ===========================================================================
__device__ __forceinline__ uint32_t smem_u32(const void* p) {
    uint32_t a;
    asm("{ .reg .u64 t; cvta.to.shared.u64 t, %1; cvt.u32.u64 %0, t; }"
        : "=r"(a) : "l"(p));
    return a;
}
__device__ __forceinline__ void cp_async16(uint32_t saddr, const void* gaddr) {
    asm volatile("cp.async.cg.shared.global [%0], [%1], 16;"
                 :: "r"(saddr), "l"(gaddr));
}
__device__ __forceinline__ void cp_commit() {
    asm volatile("cp.async.commit_group;" ::: "memory");
}
__device__ __forceinline__ void ldsm4(uint32_t* r, uint32_t addr) {
    asm volatile("ldmatrix.sync.aligned.m8n8.x4.shared.b16 {%0,%1,%2,%3}, [%4];"
                 : "=r"(r[0]), "=r"(r[1]), "=r"(r[2]), "=r"(r[3]) : "r"(addr));
}
__device__ __forceinline__ void mma16816(float* c, const uint32_t* a,
                                         uint32_t b0, uint32_t b1) {
    asm volatile(
        "mma.sync.aligned.m16n8k16.row.col.f32.bf16.bf16.f32 "
        "{%0,%1,%2,%3}, {%4,%5,%6,%7}, {%8,%9}, {%0,%1,%2,%3};"
        : "+f"(c[0]), "+f"(c[1]), "+f"(c[2]), "+f"(c[3])
        : "r"(a[0]), "r"(a[1]), "r"(a[2]), "r"(a[3]), "r"(b0), "r"(b1));
}
__device__ __forceinline__ uint32_t pack2h(__nv_bfloat16 a, __nv_bfloat16 b) {
    __nv_bfloat162 t = __halves2bfloat162(a, b);
    return *reinterpret_cast<uint32_t*>(&t);
}
__device__ __forceinline__ uint32_t pack2f(float a, float b) {
    __nv_bfloat162 t = __floats2bfloat162_rn(a, b);
    return *reinterpret_cast<uint32_t*>(&t);
}
__device__ __forceinline__ void split2(float a, float b, uint32_t& hi, uint32_t& lo) {
    __nv_bfloat16 ha = __float2bfloat16(a), hb = __float2bfloat16(b);
    hi = pack2h(ha, hb);
    lo = pack2f(a - __bfloat162float(ha), b - __bfloat162float(hb));
}
// exp(x*0.125) as a single FMUL + MUFU: ex2(x * 0.125*log2(e))
__device__ __forceinline__ float expq(float x) {
    float y;
    asm("ex2.approx.ftz.f32 %0, %1;" : "=f"(y) : "f"(x * 0.1803368801111244f));
    return y;
}

// ===========================================================================
// MERGED prologue: one launch does everything independent of the QKV GEMM.
//   z in [0,4): transpose+split weight z
//   z == 4   : RoPE sin/cos table
//   z in [5,9): RMSNorm + bf16 split, rows (z-5)*1024 + by*32 + bx
// ===========================================================================
__global__ __launch_bounds__(256) void prologue_kernel(
    const float* __restrict__ x, const float* __restrict__ sc,
    const float* __restrict__ W0, const float* __restrict__ W1,
    const float* __restrict__ W2, const float* __restrict__ W3,
    __nv_bfloat16* __restrict__ Th, __nv_bfloat16* __restrict__ Tl,
    float* __restrict__ sinT, float* __restrict__ cosT,
    __nv_bfloat16* __restrict__ ah, __nv_bfloat16* __restrict__ al)
{
    __shared__ float tile[32][33];
    __shared__ float red[256];
    int z = blockIdx.z;

    if (z == 4) {
        int idx = (blockIdx.y * 32 + blockIdx.x) * 256 + threadIdx.x;
        if (idx < SEQ * 32) {
            int pos = idx >> 5, i = idx & 31;
            float e = (2.0f * (float)i) / (float)DH;
            float theta = exp2f(-e * 19.931568569324174f);   // 1e6^-e
            float ang = (float)pos * theta;
            sinT[idx] = sinf(ang);
            cosT[idx] = cosf(ang);
        }
        return;
    }

    if (z >= 5) {
        int row = (z - 5) * 1024 + blockIdx.y * 32 + blockIdx.x;
        const float* xr = x + (size_t)row * DIM;
        float v[4];
        float ss = 0.f;
        #pragma unroll
        for (int j = 0; j < 4; j++) {
            v[j] = xr[threadIdx.x + j * 256];
            ss = fmaf(v[j], v[j], ss);
        }
        red[threadIdx.x] = ss;
        __syncthreads();
        #pragma unroll
        for (int s = 128; s > 0; s >>= 1) {
            if (threadIdx.x < s) red[threadIdx.x] += red[threadIdx.x + s];
            __syncthreads();
        }
        float r = rsqrtf(red[0] * (1.0f / DIM) + 1e-6f);
        #pragma unroll
        for (int j = 0; j < 4; j++) {
            int i = threadIdx.x + j * 256;
            float y = v[j] * r * sc[i];
            __nv_bfloat16 h = __float2bfloat16(y);
            ah[(size_t)row * DIM + i] = h;
            al[(size_t)row * DIM + i] = __float2bfloat16(y - __bfloat162float(h));
        }
        return;
    }

    const float* W = (z == 0) ? W0 : (z == 1) ? W1 : (z == 2) ? W2 : W3;
    __nv_bfloat16* th = Th + (size_t)z * DIM * DIM;
    __nv_bfloat16* tl = Tl + (size_t)z * DIM * DIM;

    int k0 = blockIdx.y * 32, n0 = blockIdx.x * 32;
    int tx = threadIdx.x & 31, ty = threadIdx.x >> 5;   // 32 x 8
    #pragma unroll
    for (int i = 0; i < 32; i += 8)
        tile[ty + i][tx] = W[(size_t)(k0 + ty + i) * DIM + n0 + tx];
    __syncthreads();
    #pragma unroll
    for (int i = 0; i < 32; i += 8) {
        float v = tile[tx][ty + i];    // = W[k0+tx][n0+ty+i]
        __nv_bfloat16 h = __float2bfloat16(v);
        float r = v - __bfloat162float(h);
        size_t o = (size_t)(n0 + ty + i) * DIM + k0 + tx;
        th[o] = h;
        tl[o] = __float2bfloat16(r);
    }
}

// ===========================================================================
// bf16-split GEMM via mma.sync. 3-stage cp.async pipeline (validated R10).
// ===========================================================================
#define A_TILE_B 20480             // 256 rows x 80 bytes
#define B_TILE_B 10240             // 128 rows x 80 bytes
#define STG_B    (2*A_TILE_B + 2*B_TILE_B)   // 61440
#define GEMM_SMEM (3*STG_B)                   // 184320 (3 stages)

__global__ __launch_bounds__(256) void mma_gemm_kernel(
    const __nv_bfloat16* __restrict__ Ah, const __nv_bfloat16* __restrict__ Al,
    const __nv_bfloat16* __restrict__ BhBase, const __nv_bfloat16* __restrict__ BlBase,
    float* __restrict__ CBase)
{
    extern __shared__ char smem[];
    uint32_t sb = smem_u32(smem);

    const int tid  = threadIdx.x;
    const int lane = tid & 31;
    const int wid  = tid >> 5;
    const int warp_m = wid & 3;
    const int warp_n = wid >> 2;
    const int which = blockIdx.x >> 3;               // weight index
    const int bm = blockIdx.y * 256;
    const int bn = (blockIdx.x & 7) * 128;

    const __nv_bfloat16* Bh = BhBase + (size_t)which * DIM * DIM;
    const __nv_bfloat16* Bl = BlBase + (size_t)which * DIM * DIM;
    float* C = CBase + (size_t)which * ROWS * DIM;

    float acc[4][8][4];
    #pragma unroll
    for (int i = 0; i < 4; i++)
        #pragma unroll
        for (int j = 0; j < 8; j++)
            #pragma unroll
            for (int q = 0; q < 4; q++) acc[i][j][q] = 0.f;

    auto load_stage = [&](int kt, int s) {
        const __nv_bfloat16* asrc[2] = {Ah, Al};
        #pragma unroll
        for (int t = 0; t < 2; t++) {
            #pragma unroll
            for (int i = 0; i < 4; i++) {
                int chunk = tid + i * 256;         // 0..1023
                int row = chunk >> 2, c = chunk & 3;
                cp_async16(sb + s * STG_B + t * A_TILE_B + row * 80 + c * 16,
                           asrc[t] + (size_t)(bm + row) * DIM + kt * 32 + c * 8);
            }
        }
        const __nv_bfloat16* bsrc[2] = {Bh, Bl};
        #pragma unroll
        for (int t = 0; t < 2; t++) {
            #pragma unroll
            for (int i = 0; i < 2; i++) {
                int chunk = tid + i * 256;         // 0..511
                int row = chunk >> 2, c = chunk & 3;
                cp_async16(sb + s * STG_B + 2 * A_TILE_B + t * B_TILE_B + row * 80 + c * 16,
                           bsrc[t] + (size_t)(bn + row) * DIM + kt * 32 + c * 8);
            }
        }
        cp_commit();
    };

    load_stage(0, 0);
    load_stage(1, 1);

    const int aRow = lane & 15;
    const int aK16 = (lane >> 4) * 16;
    const int bRow = (lane & 7) + ((lane >> 4) << 3);
    const int bK16 = ((lane >> 3) & 1) * 16;

    int sNext = 2;   // stage index for kt+2
    for (int kt = 0; kt < 32; kt++) {
        if (kt < 31) asm volatile("cp.async.wait_group 1;" ::: "memory");
        else         asm volatile("cp.async.wait_group 0;" ::: "memory");
        __syncthreads();

        if (kt + 2 < 32) load_stage(kt + 2, sNext);

        int sCur = sNext + 1; if (sCur >= 3) sCur -= 3;   // == kt % 3
        uint32_t st  = sb + sCur * STG_B;
        uint32_t aHb = st + (warp_m * 64 + aRow) * 80 + aK16;
        uint32_t aLb = aHb + A_TILE_B;
        uint32_t bHb = st + 2 * A_TILE_B + (warp_n * 64 + bRow) * 80 + bK16;
        uint32_t bLb = bHb + B_TILE_B;
        sNext = sCur;

        #pragma unroll
        for (int ks = 0; ks < 2; ks++) {
            uint32_t koff = ks * 32;
            uint32_t fah[4][4], fal[4][4], fb[4][4];
            #pragma unroll
            for (int mt = 0; mt < 4; mt++) {
                ldsm4(fah[mt], aHb + mt * 1280 + koff);
                ldsm4(fal[mt], aLb + mt * 1280 + koff);
            }
            #pragma unroll
            for (int n2 = 0; n2 < 4; n2++)
                ldsm4(fb[n2], bHb + n2 * 1280 + koff);
            #pragma unroll
            for (int mt = 0; mt < 4; mt++)
                #pragma unroll
                for (int nt = 0; nt < 8; nt++)
                    mma16816(acc[mt][nt], fah[mt],
                             fb[nt >> 1][(nt & 1) * 2], fb[nt >> 1][(nt & 1) * 2 + 1]);
            #pragma unroll
            for (int mt = 0; mt < 4; mt++)
                #pragma unroll
                for (int nt = 0; nt < 8; nt++)
                    mma16816(acc[mt][nt], fal[mt],
                             fb[nt >> 1][(nt & 1) * 2], fb[nt >> 1][(nt & 1) * 2 + 1]);
            #pragma unroll
            for (int n2 = 0; n2 < 4; n2++)
                ldsm4(fb[n2], bLb + n2 * 1280 + koff);
            #pragma unroll
            for (int mt = 0; mt < 4; mt++)
                #pragma unroll
                for (int nt = 0; nt < 8; nt++)
                    mma16816(acc[mt][nt], fah[mt],
                             fb[nt >> 1][(nt & 1) * 2], fb[nt >> 1][(nt & 1) * 2 + 1]);
        }
    }

    const int g = lane >> 2, t2 = (lane & 3) * 2;
    #pragma unroll
    for (int mt = 0; mt < 4; mt++) {
        #pragma unroll
        for (int nt = 0; nt < 8; nt++) {
            int row = bm + warp_m * 64 + mt * 16 + g;
            int col = bn + warp_n * 64 + nt * 8 + t2;
            *(float2*)&C[(size_t)row * DIM + col] =
                make_float2(acc[mt][nt][0], acc[mt][nt][1]);
            *(float2*)&C[(size_t)(row + 8) * DIM + col] =
                make_float2(acc[mt][nt][2], acc[mt][nt][3]);
        }
    }
}

// ===========================================================================
// Merged RoPE-split (float4 vectorized) + V transpose-split (4B stores).
// ===========================================================================
__global__ __launch_bounds__(256) void qkv_prep_kernel(
    const float* __restrict__ qkv,
    const float* __restrict__ sinT, const float* __restrict__ cosT,
    __nv_bfloat16* __restrict__ Qh, __nv_bfloat16* __restrict__ Ql,
    __nv_bfloat16* __restrict__ Kh, __nv_bfloat16* __restrict__ Kl,
    __nv_bfloat16* __restrict__ Vth, __nv_bfloat16* __restrict__ Vtl)
{
    __shared__ float tile[32][33];
    int bid = blockIdx.x;

    if (bid < 4096) {
        int idx = bid * 256 + threadIdx.x;     // 2^20 total
        int which = idx >> 19;                 // 0=q, 1=k
        int r   = idx & ((1 << 19) - 1);
        int row = r >> 7;                      // 128 = 16 heads * 8
        int rem = r & 127;
        int head = rem >> 3;
        int i4   = (rem & 7) * 4;

        const float* src = qkv + (size_t)which * ROWS * DIM
                               + (size_t)row * DIM + head * DH;
        int pos = row & (SEQ - 1);

        float4 sn = *(const float4*)&sinT[pos * 32 + i4];
        float4 cs = *(const float4*)&cosT[pos * 32 + i4];
        float4 x1 = *(const float4*)&src[i4];
        float4 x2 = *(const float4*)&src[i4 + 32];

        float y1a = x1.x * cs.x - x2.x * sn.x, y2a = x1.x * sn.x + x2.x * cs.x;
        float y1b = x1.y * cs.y - x2.y * sn.y, y2b = x1.y * sn.y + x2.y * cs.y;
        float y1c = x1.z * cs.z - x2.z * sn.z, y2c = x1.z * sn.z + x2.z * cs.z;
        float y1d = x1.w * cs.w - x2.w * sn.w, y2d = x1.w * sn.w + x2.w * cs.w;

        int b = row >> 11, s = row & (SEQ - 1);
        size_t o = ((size_t)(b * NH + head) * SEQ + s) * DH + i4;
        __nv_bfloat16* H = which ? Kh : Qh;
        __nv_bfloat16* L = which ? Kl : Ql;
        uint32_t h0, l0, h1, l1;
        split2(y1a, y1b, h0, l0);
        split2(y1c, y1d, h1, l1);
        *(uint2*)&H[o] = make_uint2(h0, h1);
        *(uint2*)&L[o] = make_uint2(l0, l1);
        split2(y2a, y2b, h0, l0);
        split2(y2c, y2d, h1, l1);
        *(uint2*)&H[o + 32] = make_uint2(h0, h1);
        *(uint2*)&L[o + 32] = make_uint2(l0, l1);
    } else {
        int b2 = bid - 4096;                 // [0, 4096)
        int s0 = (b2 & 63) * 32;
        int d0 = ((b2 >> 6) & 1) * 32;
        int bh = b2 >> 7;
        int b = bh >> 4, h = bh & 15;
        const float* v = qkv + (size_t)2 * ROWS * DIM;
        int tx = threadIdx.x & 31, ty = threadIdx.x >> 5;
        #pragma unroll
        for (int i = 0; i < 32; i += 8)
            tile[ty + i][tx] = v[(size_t)(b * SEQ + s0 + ty + i) * DIM + h * DH + d0 + tx];
        __syncthreads();
        int sx = threadIdx.x & 15;
        int dy = threadIdx.x >> 4;
        #pragma unroll
        for (int dd = 0; dd < 32; dd += 16) {
            int d = dy + dd;
            float va = tile[sx * 2][d];
            float vb = tile[sx * 2 + 1][d];
            uint32_t hi, lo;
            split2(va, vb, hi, lo);
            size_t o = ((size_t)(bh * DH + d0 + d)) * SEQ + s0 + sx * 2;
            *(uint32_t*)&Vth[o] = hi;
            *(uint32_t*)&Vtl[o] = lo;
        }
    }
}

// ===========================================================================
// Flash attention via mma.sync, split-bf16.
// 3-ring KV pipeline in 110.5 KB (Q buffer recycled as 3rd KV stage) +
// 128-reg body => 2 CTAs/SM AND one __syncthreads per chunk.
//   buffer b in {0,1,2} at sb + b*36864:
//     as Q (init, buf0): Qh +0, Ql +18432
//     as KV stage:       Kh +0, Kl +9216, Vh +18432, Vl +27648
//   KV(kt) lives in buf((kt+1)%3); iteration kt prefetches KV(kt+2) into
//   buf(kt%3) (consumed at kt-1, protected by the sync at top of kt).
// ===========================================================================
#define BUF_B   36864               // one buffer
#define FP      144                 // smem row pitch (bytes)
#define FL_SMEM (3*BUF_B)           // 110592

__global__ __launch_bounds__(256, 2) void flash_mma_kernel(
    const __nv_bfloat16* __restrict__ Qh_, const __nv_bfloat16* __restrict__ Ql_,
    const __nv_bfloat16* __restrict__ Kh_, const __nv_bfloat16* __restrict__ Kl_,
    const __nv_bfloat16* __restrict__ Vth_, const __nv_bfloat16* __restrict__ Vtl_,
    __nv_bfloat16* __restrict__ Oh, __nv_bfloat16* __restrict__ Ol)
{
    extern __shared__ char smem[];
    uint32_t sb = smem_u32(smem);
    const int tid = threadIdx.x, lane = tid & 31, wid = tid >> 5;
    const int bh = blockIdx.y;
    const int qt = (gridDim.x - 1) - blockIdx.x;   // heavy tiles first
    const int nkt = 2 * (qt + 1);                  // 64-key chunks
    const size_t qkoff = (size_t)bh * SEQ * DH;
    const size_t voff  = (size_t)bh * DH * SEQ;

    // Q tile load into buffer 0 (group 1)
    {
        const __nv_bfloat16* qs[2] = {Qh_ + qkoff, Ql_ + qkoff};
        #pragma unroll
        for (int i = 0; i < 8; i++) {
            int idx = tid + i * 256;           // 0..2047
            int t = idx >> 10, rem = idx & 1023;
            int row = rem >> 3, c = rem & 7;
            cp_async16(sb + t * 18432 + row * FP + c * 16,
                       qs[t] + (size_t)(qt * 128 + row) * DH + c * 8);
        }
        cp_commit();
    }

    auto load_kv = [&](int kt, int buf) {
        int k0 = kt * 64;
        uint32_t base = sb + buf * BUF_B;
        const __nv_bfloat16* ks_[2] = {Kh_ + qkoff, Kl_ + qkoff};
        const __nv_bfloat16* vs_[2] = {Vth_ + voff, Vtl_ + voff};
        #pragma unroll
        for (int i = 0; i < 4; i++) {
            int idx = tid + i * 256;           // 0..1023
            int t = idx >> 9, rem = idx & 511;
            int row = rem >> 3, c = rem & 7;
            cp_async16(base + t * 9216 + row * FP + c * 16,
                       ks_[t] + (size_t)(k0 + row) * DH + c * 8);
        }
        #pragma unroll
        for (int i = 0; i < 4; i++) {
            int idx = tid + i * 256;
            int t = idx >> 9, rem = idx & 511;
            int row = rem >> 3, c = rem & 7;   // row = dh index, c = key chunk
            cp_async16(base + 18432 + t * 9216 + row * FP + c * 16,
                       vs_[t] + (size_t)row * SEQ + k0 + c * 8);
        }
        cp_commit();
    };
    load_kv(0, 1);   // KV0 -> buf1
    load_kv(1, 2);   // KV1 -> buf2

    const int g = lane >> 2, t2 = (lane & 3) * 2;
    const int aRow = lane & 15, aK16 = (lane >> 4) * 16;
    const int bRow = (lane & 7) + ((lane >> 4) << 3);
    const int bK16 = ((lane >> 3) & 1) * 16;

    // Wait for Q (group order: Q, KV0, KV1 -> wait 2 ensures Q complete)
    asm volatile("cp.async.wait_group 2;" ::: "memory");
    __syncthreads();

    uint32_t qh[4][4], ql[4][4];
    {
        uint32_t base = sb + (wid * 16 + aRow) * FP + aK16;
        #pragma unroll
        for (int ks = 0; ks < 4; ks++) {
            ldsm4(qh[ks], base + ks * 32);
            ldsm4(ql[ks], base + 18432 + ks * 32);
        }
    }
    // buf0 (Q) is dead after the frag loads above; it becomes the 3rd KV slot.

    float o[8][4];
    #pragma unroll
    for (int nt = 0; nt < 8; nt++)
        #pragma unroll
        for (int j = 0; j < 4; j++) o[nt][j] = 0.f;
    float l0 = 0.f, l1 = 0.f;
    const int row0 = qt * 128 + wid * 16 + g;
    const int rowWarpMin = qt * 128 + wid * 16;   // warp-uniform

    for (int kt = 0; kt < nkt; kt++) {
        if (kt < nkt - 1) asm volatile("cp.async.wait_group 1;" ::: "memory");
        else              asm volatile("cp.async.wait_group 0;" ::: "memory");
        __syncthreads();

        // prefetch KV(kt+2) into the buffer consumed at kt-1 (== kt%3)
        if (kt + 2 < nkt) {
            int bufN = kt - (kt / 3) * 3;                  // kt % 3
            load_kv(kt + 2, bufN);
        }

        int bufC = (kt + 1) - ((kt + 1) / 3) * 3;          // (kt+1) % 3
        uint32_t stK = sb + bufC * BUF_B;
        uint32_t stV = stK + 18432;

        float S[8][4];
        #pragma unroll
        for (int nt = 0; nt < 8; nt++)
            #pragma unroll
            for (int j = 0; j < 4; j++) S[nt][j] = 0.f;

        #pragma unroll
        for (int ks = 0; ks < 4; ks++) {
            uint32_t fkh[4][4], fkl[4][4];
            #pragma unroll
            for (int n2 = 0; n2 < 4; n2++) {
                uint32_t a = stK + (n2 * 16 + bRow) * FP + bK16 + ks * 32;
                ldsm4(fkh[n2], a);
                ldsm4(fkl[n2], a + 9216);
            }
            #pragma unroll
            for (int nt = 0; nt < 8; nt++) {
                mma16816(S[nt], qh[ks], fkh[nt >> 1][(nt & 1) * 2], fkh[nt >> 1][(nt & 1) * 2 + 1]);
                mma16816(S[nt], qh[ks], fkl[nt >> 1][(nt & 1) * 2], fkl[nt >> 1][(nt & 1) * 2 + 1]);
                mma16816(S[nt], ql[ks], fkh[nt >> 1][(nt & 1) * 2], fkh[nt >> 1][(nt & 1) * 2 + 1]);
            }
        }

        // ---- softmax + pack P; warp-uniform fast path ----
        uint32_t pah[4][4], pal[4][4];
        int k0 = kt * 64;
        if (k0 + 63 <= rowWarpMin) {
            #pragma unroll
            for (int nt = 0; nt < 8; nt++) {
                float p0 = expq(S[nt][0]);
                float p1 = expq(S[nt][1]);
                float p2 = expq(S[nt][2]);
                float p3 = expq(S[nt][3]);
                l0 += p0 + p1;
                l1 += p2 + p3;
                __nv_bfloat16 h0 = __float2bfloat16(p0), h1 = __float2bfloat16(p1);
                __nv_bfloat16 h2 = __float2bfloat16(p2), h3 = __float2bfloat16(p3);
                float r0 = p0 - __bfloat162float(h0), r1 = p1 - __bfloat162float(h1);
                float r2 = p2 - __bfloat162float(h2), r3 = p3 - __bfloat162float(h3);
                int ks2 = nt >> 1, off = (nt & 1) * 2;
                pah[ks2][off]     = pack2h(h0, h1);
                pah[ks2][off + 1] = pack2h(h2, h3);
                pal[ks2][off]     = pack2f(r0, r1);
                pal[ks2][off + 1] = pack2f(r2, r3);
            }
        } else {
            #pragma unroll
            for (int nt = 0; nt < 8; nt++) {
                int col = k0 + nt * 8 + t2;
                float p0 = (col     <= row0)     ? expq(S[nt][0]) : 0.f;
                float p1 = (col + 1 <= row0)     ? expq(S[nt][1]) : 0.f;
                float p2 = (col     <= row0 + 8) ? expq(S[nt][2]) : 0.f;
                float p3 = (col + 1 <= row0 + 8) ? expq(S[nt][3]) : 0.f;
                l0 += p0 + p1;
                l1 += p2 + p3;
                __nv_bfloat16 h0 = __float2bfloat16(p0), h1 = __float2bfloat16(p1);
                __nv_bfloat16 h2 = __float2bfloat16(p2), h3 = __float2bfloat16(p3);
                float r0 = p0 - __bfloat162float(h0), r1 = p1 - __bfloat162float(h1);
                float r2 = p2 - __bfloat162float(h2), r3 = p3 - __bfloat162float(h3);
                int ks2 = nt >> 1, off = (nt & 1) * 2;
                pah[ks2][off]     = pack2h(h0, h1);
                pah[ks2][off + 1] = pack2h(h2, h3);
                pal[ks2][off]     = pack2f(r0, r1);
                pal[ks2][off + 1] = pack2f(r2, r3);
            }
        }

        #pragma unroll
        for (int ks2 = 0; ks2 < 4; ks2++) {
            uint32_t fvh[4][4], fvl[4][4];
            #pragma unroll
            for (int n2 = 0; n2 < 4; n2++) {
                uint32_t a = stV + (n2 * 16 + bRow) * FP + bK16 + ks2 * 32;
                ldsm4(fvh[n2], a);
                ldsm4(fvl[n2], a + 9216);
            }
            #pragma unroll
            for (int nt = 0; nt < 8; nt++) {
                mma16816(o[nt], pah[ks2], fvh[nt >> 1][(nt & 1) * 2], fvh[nt >> 1][(nt & 1) * 2 + 1]);
                mma16816(o[nt], pah[ks2], fvl[nt >> 1][(nt & 1) * 2], fvl[nt >> 1][(nt & 1) * 2 + 1]);
                mma16816(o[nt], pal[ks2], fvh[nt >> 1][(nt & 1) * 2], fvh[nt >> 1][(nt & 1) * 2 + 1]);
            }
        }
    }

    l0 += __shfl_xor_sync(0xFFFFFFFFu, l0, 1);
    l0 += __shfl_xor_sync(0xFFFFFFFFu, l0, 2);
    l1 += __shfl_xor_sync(0xFFFFFFFFu, l1, 1);
    l1 += __shfl_xor_sync(0xFFFFFFFFu, l1, 2);
    float inv0 = 1.0f / l0, inv1 = 1.0f / l1;

    int b = bh >> 4, h = bh & 15;
    int srow = qt * 128 + wid * 16 + g;
    #pragma unroll
    for (int nt = 0; nt < 8; nt++) {
        int d = nt * 8 + t2;
        size_t o0 = (size_t)(b * SEQ + srow) * DIM + h * DH + d;
        size_t o1 = (size_t)(b * SEQ + srow + 8) * DIM + h * DH + d;
        uint32_t hi, lo;
        split2(o[nt][0] * inv0, o[nt][1] * inv0, hi, lo);
        *(uint32_t*)&Oh[o0] = hi;  *(uint32_t*)&Ol[o0] = lo;
        split2(o[nt][2] * inv1, o[nt][3] * inv1, hi, lo);
        *(uint32_t*)&Oh[o1] = hi;  *(uint32_t*)&Ol[o1] = lo;
    }
}

// ===========================================================================
// Launch
// ===========================================================================
extern "C" void kernel_launch(void* const* d_in, const int* in_sizes, int n_in,
                              void* d_out, int out_size)
{
    (void)in_sizes; (void)n_in; (void)out_size;
    const float* x  = (const float*)d_in[0];
    const float* ns = (const float*)d_in[1];
    const float* Wq = (const float*)d_in[2];
    const float* Wk = (const float*)d_in[3];
    const float* Wv = (const float*)d_in[4];
    const float* Wo = (const float*)d_in[5];
    float* out = (float*)d_out;

    float *qkv, *sinT, *cosT;
    __nv_bfloat16 *ah, *al, *th, *tl, *qhp, *qlp, *khp, *klp, *vth, *vtl;
    cudaGetSymbolAddress((void**)&qkv, g_qkv);
    cudaGetSymbolAddress((void**)&sinT, g_sinT);
    cudaGetSymbolAddress((void**)&cosT, g_cosT);
    cudaGetSymbolAddress((void**)&ah, g_ah);
    cudaGetSymbolAddress((void**)&al, g_al);
    cudaGetSymbolAddress((void**)&th, g_th);
    cudaGetSymbolAddress((void**)&tl, g_tl);
    cudaGetSymbolAddress((void**)&qhp, g_qh);
    cudaGetSymbolAddress((void**)&qlp, g_ql);
    cudaGetSymbolAddress((void**)&khp, g_kh);
    cudaGetSymbolAddress((void**)&klp, g_kl);
    cudaGetSymbolAddress((void**)&vth, g_vth);
    cudaGetSymbolAddress((void**)&vtl, g_vtl);

    cudaFuncSetAttribute(mma_gemm_kernel,
                         cudaFuncAttributeMaxDynamicSharedMemorySize, GEMM_SMEM);
    cudaFuncSetAttribute(flash_mma_kernel,
                         cudaFuncAttributeMaxDynamicSharedMemorySize, FL_SMEM);

    prologue_kernel<<<dim3(DIM / 32, DIM / 32, 9), 256>>>(
        x, ns, Wq, Wk, Wv, Wo, th, tl, sinT, cosT, ah, al);

    mma_gemm_kernel<<<dim3(3 * (DIM / 128), ROWS / 256), 256, GEMM_SMEM>>>(
        ah, al, th, tl, qkv);

    qkv_prep_kernel<<<4096 + 4096, 256>>>(
        qkv, sinT, cosT, qhp, qlp, khp, klp, vth, vtl);

    flash_mma_kernel<<<dim3(SEQ / 128, BATCH * NH), 256, FL_SMEM>>>(
        qhp, qlp, khp, klp, vth, vtl, ah, al);

    mma_gemm_kernel<<<dim3(DIM / 128, ROWS / 256), 256, GEMM_SMEM>>>(
        ah, al, th + (size_t)3 * DIM * DIM, tl + (size_t)3 * DIM * DIM, out);
}

// round 15
// speedup vs baseline: 1.0254x; 1.0098x over previous
#include <cuda_runtime.h>
#include <cuda_bf16.h>
#include <stdint.h>
#include <math.h>

#define BATCH 2
#define SEQ   2048
#define DIM   1024
#define ROWS  (BATCH*SEQ)   // 4096
#define NH    16
#define DH    64

// Scratch (allocation-free rule: __device__ globals)
__device__ float g_qkv[3*ROWS*DIM];          // Q,K,V fp32 outputs
__device__ float g_sinT[SEQ*32];             // RoPE tables [pos][i]
__device__ float g_cosT[SEQ*32];
__device__ __nv_bfloat16 g_ah[ROWS*DIM];     // x_norm split hi; later attn-out hi
__device__ __nv_bfloat16 g_al[ROWS*DIM];     // x_norm split lo; later attn-out lo
__device__ __nv_bfloat16 g_th[4*DIM*DIM];    // W^T split hi [4][N][K] (q,k,v,o)
__device__ __nv_bfloat16 g_tl[4*DIM*DIM];    // W^T split lo
// attention operands, head-contiguous layouts
__device__ __nv_bfloat16 g_qh[ROWS*DIM];     // Q hi (roped) [bh][s][d]
__device__ __nv_bfloat16 g_ql[ROWS*DIM];
__device__ __nv_bfloat16 g_kh[ROWS*DIM];     // K hi (roped) [bh][s][d]
__device__ __nv_bfloat16 g_kl[ROWS*DIM];
__device__ __nv_bfloat16 g_vth[ROWS*DIM];    // V^T hi [bh][d][s]
__device__ __nv_bfloat16 g_vtl[ROWS*DIM];

// ===========================================================================
// Portable (compute_103-safe) PTX helpers: mma.sync / ldmatrix / cp.async
// ===========================================================================
__device__ __forceinline__ uint32_t smem_u32(const void* p) {
    uint32_t a;
    asm("{ .reg .u64 t; cvta.to.shared.u64 t, %1; cvt.u32.u64 %0, t; }"
        : "=r"(a) : "l"(p));
    return a;
}
__device__ __forceinline__ void cp_async16(uint32_t saddr, const void* gaddr) {
    asm volatile("cp.async.cg.shared.global [%0], [%1], 16;"
                 :: "r"(saddr), "l"(gaddr));
}
__device__ __forceinline__ void cp_commit() {
    asm volatile("cp.async.commit_group;" ::: "memory");
}
__device__ __forceinline__ void ldsm4(uint32_t* r, uint32_t addr) {
    asm volatile("ldmatrix.sync.aligned.m8n8.x4.shared.b16 {%0,%1,%2,%3}, [%4];"
                 : "=r"(r[0]), "=r"(r[1]), "=r"(r[2]), "=r"(r[3]) : "r"(addr));
}
__device__ __forceinline__ void mma16816(float* c, const uint32_t* a,
                                         uint32_t b0, uint32_t b1) {
    asm volatile(
        "mma.sync.aligned.m16n8k16.row.col.f32.bf16.bf16.f32 "
        "{%0,%1,%2,%3}, {%4,%5,%6,%7}, {%8,%9}, {%0,%1,%2,%3};"
        : "+f"(c[0]), "+f"(c[1]), "+f"(c[2]), "+f"(c[3])
        : "r"(a[0]), "r"(a[1]), "r"(a[2]), "r"(a[3]), "r"(b0), "r"(b1));
}
__device__ __forceinline__ uint32_t pack2h(__nv_bfloat16 a, __nv_bfloat16 b) {
    __nv_bfloat162 t = __halves2bfloat162(a, b);
    return *reinterpret_cast<uint32_t*>(&t);
}
__device__ __forceinline__ uint32_t pack2f(float a, float b) {
    __nv_bfloat162 t = __floats2bfloat162_rn(a, b);
    return *reinterpret_cast<uint32_t*>(&t);
}
__device__ __forceinline__ void split2(float a, float b, uint32_t& hi, uint32_t& lo) {
    __nv_bfloat16 ha = __float2bfloat16(a), hb = __float2bfloat16(b);
    hi = pack2h(ha, hb);
    lo = pack2f(a - __bfloat162float(ha), b - __bfloat162float(hb));
}
// exp(x*0.125) as a single FMUL + MUFU: ex2(x * 0.125*log2(e))
__device__ __forceinline__ float expq(float x) {
    float y;
    asm("ex2.approx.ftz.f32 %0, %1;" : "=f"(y) : "f"(x * 0.1803368801111244f));
    return y;
}

// ===========================================================================
// MERGED prologue (unchanged from R14)
// ===========================================================================
__global__ __launch_bounds__(256) void prologue_kernel(
    const float* __restrict__ x, const float* __restrict__ sc,
    const float* __restrict__ W0, const float* __restrict__ W1,
    const float* __restrict__ W2, const float* __restrict__ W3,
    __nv_bfloat16* __restrict__ Th, __nv_bfloat16* __restrict__ Tl,
    float* __restrict__ sinT, float* __restrict__ cosT,
    __nv_bfloat16* __restrict__ ah, __nv_bfloat16* __restrict__ al)
{
    __shared__ float tile[32][33];
    __shared__ float red[256];
    int z = blockIdx.z;

    if (z == 4) {
        int idx = (blockIdx.y * 32 + blockIdx.x) * 256 + threadIdx.x;
        if (idx < SEQ * 32) {
            int pos = idx >> 5, i = idx & 31;
            float e = (2.0f * (float)i) / (float)DH;
            float theta = exp2f(-e * 19.931568569324174f);   // 1e6^-e
            float ang = (float)pos * theta;
            sinT[idx] = sinf(ang);
            cosT[idx] = cosf(ang);
        }
        return;
    }

    if (z >= 5) {
        int row = (z - 5) * 1024 + blockIdx.y * 32 + blockIdx.x;
        const float* xr = x + (size_t)row * DIM;
        float v[4];
        float ss = 0.f;
        #pragma unroll
        for (int j = 0; j < 4; j++) {
            v[j] = xr[threadIdx.x + j * 256];
            ss = fmaf(v[j], v[j], ss);
        }
        red[threadIdx.x] = ss;
        __syncthreads();
        #pragma unroll
        for (int s = 128; s > 0; s >>= 1) {
            if (threadIdx.x < s) red[threadIdx.x] += red[threadIdx.x + s];
            __syncthreads();
        }
        float r = rsqrtf(red[0] * (1.0f / DIM) + 1e-6f);
        #pragma unroll
        for (int j = 0; j < 4; j++) {
            int i = threadIdx.x + j * 256;
            float y = v[j] * r * sc[i];
            __nv_bfloat16 h = __float2bfloat16(y);
            ah[(size_t)row * DIM + i] = h;
            al[(size_t)row * DIM + i] = __float2bfloat16(y - __bfloat162float(h));
        }
        return;
    }

    const float* W = (z == 0) ? W0 : (z == 1) ? W1 : (z == 2) ? W2 : W3;
    __nv_bfloat16* th = Th + (size_t)z * DIM * DIM;
    __nv_bfloat16* tl = Tl + (size_t)z * DIM * DIM;

    int k0 = blockIdx.y * 32, n0 = blockIdx.x * 32;
    int tx = threadIdx.x & 31, ty = threadIdx.x >> 5;   // 32 x 8
    #pragma unroll
    for (int i = 0; i < 32; i += 8)
        tile[ty + i][tx] = W[(size_t)(k0 + ty + i) * DIM + n0 + tx];
    __syncthreads();
    #pragma unroll
    for (int i = 0; i < 32; i += 8) {
        float v = tile[tx][ty + i];    // = W[k0+tx][n0+ty+i]
        __nv_bfloat16 h = __float2bfloat16(v);
        float r = v - __bfloat162float(h);
        size_t o = (size_t)(n0 + ty + i) * DIM + k0 + tx;
        th[o] = h;
        tl[o] = __float2bfloat16(r);
    }
}

// ===========================================================================
// bf16-split GEMM via mma.sync. 3-stage cp.async pipeline (validated R10).
// ===========================================================================
#define A_TILE_B 20480             // 256 rows x 80 bytes
#define B_TILE_B 10240             // 128 rows x 80 bytes
#define STG_B    (2*A_TILE_B + 2*B_TILE_B)   // 61440
#define GEMM_SMEM (3*STG_B)                   // 184320 (3 stages)

__global__ __launch_bounds__(256) void mma_gemm_kernel(
    const __nv_bfloat16* __restrict__ Ah, const __nv_bfloat16* __restrict__ Al,
    const __nv_bfloat16* __restrict__ BhBase, const __nv_bfloat16* __restrict__ BlBase,
    float* __restrict__ CBase)
{
    extern __shared__ char smem[];
    uint32_t sb = smem_u32(smem);

    const int tid  = threadIdx.x;
    const int lane = tid & 31;
    const int wid  = tid >> 5;
    const int warp_m = wid & 3;
    const int warp_n = wid >> 2;
    const int which = blockIdx.x >> 3;               // weight index
    const int bm = blockIdx.y * 256;
    const int bn = (blockIdx.x & 7) * 128;

    const __nv_bfloat16* Bh = BhBase + (size_t)which * DIM * DIM;
    const __nv_bfloat16* Bl = BlBase + (size_t)which * DIM * DIM;
    float* C = CBase + (size_t)which * ROWS * DIM;

    float acc[4][8][4];
    #pragma unroll
    for (int i = 0; i < 4; i++)
        #pragma unroll
        for (int j = 0; j < 8; j++)
            #pragma unroll
            for (int q = 0; q < 4; q++) acc[i][j][q] = 0.f;

    auto load_stage = [&](int kt, int s) {
        const __nv_bfloat16* asrc[2] = {Ah, Al};
        #pragma unroll
        for (int t = 0; t < 2; t++) {
            #pragma unroll
            for (int i = 0; i < 4; i++) {
                int chunk = tid + i * 256;         // 0..1023
                int row = chunk >> 2, c = chunk & 3;
                cp_async16(sb + s * STG_B + t * A_TILE_B + row * 80 + c * 16,
                           asrc[t] + (size_t)(bm + row) * DIM + kt * 32 + c * 8);
            }
        }
        const __nv_bfloat16* bsrc[2] = {Bh, Bl};
        #pragma unroll
        for (int t = 0; t < 2; t++) {
            #pragma unroll
            for (int i = 0; i < 2; i++) {
                int chunk = tid + i * 256;         // 0..511
                int row = chunk >> 2, c = chunk & 3;
                cp_async16(sb + s * STG_B + 2 * A_TILE_B + t * B_TILE_B + row * 80 + c * 16,
                           bsrc[t] + (size_t)(bn + row) * DIM + kt * 32 + c * 8);
            }
        }
        cp_commit();
    };

    load_stage(0, 0);
    load_stage(1, 1);

    const int aRow = lane & 15;
    const int aK16 = (lane >> 4) * 16;
    const int bRow = (lane & 7) + ((lane >> 4) << 3);
    const int bK16 = ((lane >> 3) & 1) * 16;

    int sNext = 2;   // stage index for kt+2
    for (int kt = 0; kt < 32; kt++) {
        if (kt < 31) asm volatile("cp.async.wait_group 1;" ::: "memory");
        else         asm volatile("cp.async.wait_group 0;" ::: "memory");
        __syncthreads();

        if (kt + 2 < 32) load_stage(kt + 2, sNext);

        int sCur = sNext + 1; if (sCur >= 3) sCur -= 3;   // == kt % 3
        uint32_t st  = sb + sCur * STG_B;
        uint32_t aHb = st + (warp_m * 64 + aRow) * 80 + aK16;
        uint32_t aLb = aHb + A_TILE_B;
        uint32_t bHb = st + 2 * A_TILE_B + (warp_n * 64 + bRow) * 80 + bK16;
        uint32_t bLb = bHb + B_TILE_B;
        sNext = sCur;

        #pragma unroll
        for (int ks = 0; ks < 2; ks++) {
            uint32_t koff = ks * 32;
            uint32_t fah[4][4], fal[4][4], fb[4][4];
            #pragma unroll
            for (int mt = 0; mt < 4; mt++) {
                ldsm4(fah[mt], aHb + mt * 1280 + koff);
                ldsm4(fal[mt], aLb + mt * 1280 + koff);
            }
            #pragma unroll
            for (int n2 = 0; n2 < 4; n2++)
                ldsm4(fb[n2], bHb + n2 * 1280 + koff);
            #pragma unroll
            for (int mt = 0; mt < 4; mt++)
                #pragma unroll
                for (int nt = 0; nt < 8; nt++)
                    mma16816(acc[mt][nt], fah[mt],
                             fb[nt >> 1][(nt & 1) * 2], fb[nt >> 1][(nt & 1) * 2 + 1]);
            #pragma unroll
            for (int mt = 0; mt < 4; mt++)
                #pragma unroll
                for (int nt = 0; nt < 8; nt++)
                    mma16816(acc[mt][nt], fal[mt],
                             fb[nt >> 1][(nt & 1) * 2], fb[nt >> 1][(nt & 1) * 2 + 1]);
            #pragma unroll
            for (int n2 = 0; n2 < 4; n2++)
                ldsm4(fb[n2], bLb + n2 * 1280 + koff);
            #pragma unroll
            for (int mt = 0; mt < 4; mt++)
                #pragma unroll
                for (int nt = 0; nt < 8; nt++)
                    mma16816(acc[mt][nt], fah[mt],
                             fb[nt >> 1][(nt & 1) * 2], fb[nt >> 1][(nt & 1) * 2 + 1]);
        }
    }

    const int g = lane >> 2, t2 = (lane & 3) * 2;
    #pragma unroll
    for (int mt = 0; mt < 4; mt++) {
        #pragma unroll
        for (int nt = 0; nt < 8; nt++) {
            int row = bm + warp_m * 64 + mt * 16 + g;
            int col = bn + warp_n * 64 + nt * 8 + t2;
            *(float2*)&C[(size_t)row * DIM + col] =
                make_float2(acc[mt][nt][0], acc[mt][nt][1]);
            *(float2*)&C[(size_t)(row + 8) * DIM + col] =
                make_float2(acc[mt][nt][2], acc[mt][nt][3]);
        }
    }
}

// ===========================================================================
// Merged RoPE-split (float4 vectorized) + V transpose-split (4B stores).
// ===========================================================================
__global__ __launch_bounds__(256) void qkv_prep_kernel(
    const float* __restrict__ qkv,
    const float* __restrict__ sinT, const float* __restrict__ cosT,
    __nv_bfloat16* __restrict__ Qh, __nv_bfloat16* __restrict__ Ql,
    __nv_bfloat16* __restrict__ Kh, __nv_bfloat16* __restrict__ Kl,
    __nv_bfloat16* __restrict__ Vth, __nv_bfloat16* __restrict__ Vtl)
{
    __shared__ float tile[32][33];
    int bid = blockIdx.x;

    if (bid < 4096) {
        int idx = bid * 256 + threadIdx.x;     // 2^20 total
        int which = idx >> 19;                 // 0=q, 1=k
        int r   = idx & ((1 << 19) - 1);
        int row = r >> 7;                      // 128 = 16 heads * 8
        int rem = r & 127;
        int head = rem >> 3;
        int i4   = (rem & 7) * 4;

        const float* src = qkv + (size_t)which * ROWS * DIM
                               + (size_t)row * DIM + head * DH;
        int pos = row & (SEQ - 1);

        float4 sn = *(const float4*)&sinT[pos * 32 + i4];
        float4 cs = *(const float4*)&cosT[pos * 32 + i4];
        float4 x1 = *(const float4*)&src[i4];
        float4 x2 = *(const float4*)&src[i4 + 32];

        float y1a = x1.x * cs.x - x2.x * sn.x, y2a = x1.x * sn.x + x2.x * cs.x;
        float y1b = x1.y * cs.y - x2.y * sn.y, y2b = x1.y * sn.y + x2.y * cs.y;
        float y1c = x1.z * cs.z - x2.z * sn.z, y2c = x1.z * sn.z + x2.z * cs.z;
        float y1d = x1.w * cs.w - x2.w * sn.w, y2d = x1.w * sn.w + x2.w * cs.w;

        int b = row >> 11, s = row & (SEQ - 1);
        size_t o = ((size_t)(b * NH + head) * SEQ + s) * DH + i4;
        __nv_bfloat16* H = which ? Kh : Qh;
        __nv_bfloat16* L = which ? Kl : Ql;
        uint32_t h0, l0, h1, l1;
        split2(y1a, y1b, h0, l0);
        split2(y1c, y1d, h1, l1);
        *(uint2*)&H[o] = make_uint2(h0, h1);
        *(uint2*)&L[o] = make_uint2(l0, l1);
        split2(y2a, y2b, h0, l0);
        split2(y2c, y2d, h1, l1);
        *(uint2*)&H[o + 32] = make_uint2(h0, h1);
        *(uint2*)&L[o + 32] = make_uint2(l0, l1);
    } else {
        int b2 = bid - 4096;                 // [0, 4096)
        int s0 = (b2 & 63) * 32;
        int d0 = ((b2 >> 6) & 1) * 32;
        int bh = b2 >> 7;
        int b = bh >> 4, h = bh & 15;
        const float* v = qkv + (size_t)2 * ROWS * DIM;
        int tx = threadIdx.x & 31, ty = threadIdx.x >> 5;
        #pragma unroll
        for (int i = 0; i < 32; i += 8)
            tile[ty + i][tx] = v[(size_t)(b * SEQ + s0 + ty + i) * DIM + h * DH + d0 + tx];
        __syncthreads();
        int sx = threadIdx.x & 15;
        int dy = threadIdx.x >> 4;
        #pragma unroll
        for (int dd = 0; dd < 32; dd += 16) {
            int d = dy + dd;
            float va = tile[sx * 2][d];
            float vb = tile[sx * 2 + 1][d];
            uint32_t hi, lo;
            split2(va, vb, hi, lo);
            size_t o = ((size_t)(bh * DH + d0 + d)) * SEQ + s0 + sx * 2;
            *(uint32_t*)&Vth[o] = hi;
            *(uint32_t*)&Vtl[o] = lo;
        }
    }
}

// ===========================================================================
// Flash attention via mma.sync, split-bf16.
// 4 warps x 32 q-rows (2 m-tiles/warp): K/V fragment loads amortized over
// 2x the MMAs -> CTA LDSM traffic halved. 128 threads, 2 CTAs/SM,
// 2-stage KV ring, Q resident in its own smem region.
// ===========================================================================
#define FP      144                 // smem row pitch (bytes)
#define FQ_OFF  0                   // Qh @0, Ql @18432 (128 rows x 144)
#define FK_OFF  36864               // + stage*18432; Kh +0, Kl +9216
#define FV_OFF  73728               // + stage*18432; Vh +0, Vl +9216
#define FL_SMEM 110592

__global__ __launch_bounds__(128, 2) void flash_mma_kernel(
    const __nv_bfloat16* __restrict__ Qh_, const __nv_bfloat16* __restrict__ Ql_,
    const __nv_bfloat16* __restrict__ Kh_, const __nv_bfloat16* __restrict__ Kl_,
    const __nv_bfloat16* __restrict__ Vth_, const __nv_bfloat16* __restrict__ Vtl_,
    __nv_bfloat16* __restrict__ Oh, __nv_bfloat16* __restrict__ Ol)
{
    extern __shared__ char smem[];
    uint32_t sb = smem_u32(smem);
    const int tid = threadIdx.x, lane = tid & 31, wid = tid >> 5;   // wid 0..3
    const int bh = blockIdx.y;
    const int qt = (gridDim.x - 1) - blockIdx.x;   // heavy tiles first
    const int nkt = 2 * (qt + 1);                  // 64-key chunks
    const size_t qkoff = (size_t)bh * SEQ * DH;
    const size_t voff  = (size_t)bh * DH * SEQ;

    // Q tile load (once)
    {
        const __nv_bfloat16* qs[2] = {Qh_ + qkoff, Ql_ + qkoff};
        #pragma unroll
        for (int i = 0; i < 16; i++) {
            int idx = tid + i * 128;           // 0..2047
            int t = idx >> 10, rem = idx & 1023;
            int row = rem >> 3, c = rem & 7;
            cp_async16(sb + FQ_OFF + t * 18432 + row * FP + c * 16,
                       qs[t] + (size_t)(qt * 128 + row) * DH + c * 8);
        }
        cp_commit();
    }

    auto load_kv = [&](int kt, int s) {
        int k0 = kt * 64;
        const __nv_bfloat16* ks_[2] = {Kh_ + qkoff, Kl_ + qkoff};
        const __nv_bfloat16* vs_[2] = {Vth_ + voff, Vtl_ + voff};
        #pragma unroll
        for (int i = 0; i < 8; i++) {
            int idx = tid + i * 128;           // 0..1023
            int t = idx >> 9, rem = idx & 511;
            int row = rem >> 3, c = rem & 7;
            cp_async16(sb + FK_OFF + s * 18432 + t * 9216 + row * FP + c * 16,
                       ks_[t] + (size_t)(k0 + row) * DH + c * 8);
        }
        #pragma unroll
        for (int i = 0; i < 8; i++) {
            int idx = tid + i * 128;
            int t = idx >> 9, rem = idx & 511;
            int row = rem >> 3, c = rem & 7;   // row = dh index, c = key chunk
            cp_async16(sb + FV_OFF + s * 18432 + t * 9216 + row * FP + c * 16,
                       vs_[t] + (size_t)row * SEQ + k0 + c * 8);
        }
        cp_commit();
    };
    load_kv(0, 0);
    load_kv(1, 1);

    const int g = lane >> 2, t2 = (lane & 3) * 2;
    const int aRow = lane & 15, aK16 = (lane >> 4) * 16;
    const int bRow = (lane & 7) + ((lane >> 4) << 3);
    const int bK16 = ((lane >> 3) & 1) * 16;

    asm volatile("cp.async.wait_group 2;" ::: "memory");
    __syncthreads();

    // Q fragments resident: 2 m-tiles x 4 k-steps x (hi, lo)
    uint32_t qh[2][4][4], ql[2][4][4];
    #pragma unroll
    for (int mt = 0; mt < 2; mt++) {
        uint32_t base = sb + FQ_OFF + (wid * 32 + mt * 16 + aRow) * FP + aK16;
        #pragma unroll
        for (int ks = 0; ks < 4; ks++) {
            ldsm4(qh[mt][ks], base + ks * 32);
            ldsm4(ql[mt][ks], base + 18432 + ks * 32);
        }
    }

    float o[2][8][4];
    #pragma unroll
    for (int mt = 0; mt < 2; mt++)
        #pragma unroll
        for (int nt = 0; nt < 8; nt++)
            #pragma unroll
            for (int j = 0; j < 4; j++) o[mt][nt][j] = 0.f;
    float lsum[2][2] = {{0.f, 0.f}, {0.f, 0.f}};
    const int rowW = qt * 128 + wid * 32;   // warp-uniform base row

    for (int kt = 0; kt < nkt; kt++) {
        if (kt < nkt - 1) asm volatile("cp.async.wait_group 1;" ::: "memory");
        else              asm volatile("cp.async.wait_group 0;" ::: "memory");
        __syncthreads();

        uint32_t stK = sb + FK_OFF + (kt & 1) * 18432;
        uint32_t stV = sb + FV_OFF + (kt & 1) * 18432;

        // ---- S = Q K^T, both m-tiles share each K fragment load ----
        float S[2][8][4];
        #pragma unroll
        for (int mt = 0; mt < 2; mt++)
            #pragma unroll
            for (int nt = 0; nt < 8; nt++)
                #pragma unroll
                for (int j = 0; j < 4; j++) S[mt][nt][j] = 0.f;

        #pragma unroll
        for (int ks = 0; ks < 4; ks++) {
            uint32_t fkh[4][4], fkl[4][4];
            #pragma unroll
            for (int n2 = 0; n2 < 4; n2++) {
                uint32_t a = stK + (n2 * 16 + bRow) * FP + bK16 + ks * 32;
                ldsm4(fkh[n2], a);
                ldsm4(fkl[n2], a + 9216);
            }
            #pragma unroll
            for (int mt = 0; mt < 2; mt++)
                #pragma unroll
                for (int nt = 0; nt < 8; nt++) {
                    mma16816(S[mt][nt], qh[mt][ks], fkh[nt >> 1][(nt & 1) * 2], fkh[nt >> 1][(nt & 1) * 2 + 1]);
                    mma16816(S[mt][nt], qh[mt][ks], fkl[nt >> 1][(nt & 1) * 2], fkl[nt >> 1][(nt & 1) * 2 + 1]);
                    mma16816(S[mt][nt], ql[mt][ks], fkh[nt >> 1][(nt & 1) * 2], fkh[nt >> 1][(nt & 1) * 2 + 1]);
                }
        }

        // ---- softmax + pack P, per m-tile (warp-uniform fast path) ----
        uint32_t pah[2][4][4], pal[2][4][4];
        int k0 = kt * 64;
        #pragma unroll
        for (int mt = 0; mt < 2; mt++) {
            int rowMin = rowW + mt * 16;
            int row0 = rowMin + g;
            if (k0 + 63 <= rowMin) {
                #pragma unroll
                for (int nt = 0; nt < 8; nt++) {
                    float p0 = expq(S[mt][nt][0]);
                    float p1 = expq(S[mt][nt][1]);
                    float p2 = expq(S[mt][nt][2]);
                    float p3 = expq(S[mt][nt][3]);
                    lsum[mt][0] += p0 + p1;
                    lsum[mt][1] += p2 + p3;
                    __nv_bfloat16 h0 = __float2bfloat16(p0), h1 = __float2bfloat16(p1);
                    __nv_bfloat16 h2 = __float2bfloat16(p2), h3 = __float2bfloat16(p3);
                    float r0 = p0 - __bfloat162float(h0), r1 = p1 - __bfloat162float(h1);
                    float r2 = p2 - __bfloat162float(h2), r3 = p3 - __bfloat162float(h3);
                    int ks2 = nt >> 1, off = (nt & 1) * 2;
                    pah[mt][ks2][off]     = pack2h(h0, h1);
                    pah[mt][ks2][off + 1] = pack2h(h2, h3);
                    pal[mt][ks2][off]     = pack2f(r0, r1);
                    pal[mt][ks2][off + 1] = pack2f(r2, r3);
                }
            } else {
                #pragma unroll
                for (int nt = 0; nt < 8; nt++) {
                    int col = k0 + nt * 8 + t2;
                    float p0 = (col     <= row0)     ? expq(S[mt][nt][0]) : 0.f;
                    float p1 = (col + 1 <= row0)     ? expq(S[mt][nt][1]) : 0.f;
                    float p2 = (col     <= row0 + 8) ? expq(S[mt][nt][2]) : 0.f;
                    float p3 = (col + 1 <= row0 + 8) ? expq(S[mt][nt][3]) : 0.f;
                    lsum[mt][0] += p0 + p1;
                    lsum[mt][1] += p2 + p3;
                    __nv_bfloat16 h0 = __float2bfloat16(p0), h1 = __float2bfloat16(p1);
                    __nv_bfloat16 h2 = __float2bfloat16(p2), h3 = __float2bfloat16(p3);
                    float r0 = p0 - __bfloat162float(h0), r1 = p1 - __bfloat162float(h1);
                    float r2 = p2 - __bfloat162float(h2), r3 = p3 - __bfloat162float(h3);
                    int ks2 = nt >> 1, off = (nt & 1) * 2;
                    pah[mt][ks2][off]     = pack2h(h0, h1);
                    pah[mt][ks2][off + 1] = pack2h(h2, h3);
                    pal[mt][ks2][off]     = pack2f(r0, r1);
                    pal[mt][ks2][off + 1] = pack2f(r2, r3);
                }
            }
        }

        // ---- O += P V, both m-tiles share each V fragment load ----
        #pragma unroll
        for (int ks2 = 0; ks2 < 4; ks2++) {
            uint32_t fvh[4][4], fvl[4][4];
            #pragma unroll
            for (int n2 = 0; n2 < 4; n2++) {
                uint32_t a = stV + (n2 * 16 + bRow) * FP + bK16 + ks2 * 32;
                ldsm4(fvh[n2], a);
                ldsm4(fvl[n2], a + 9216);
            }
            #pragma unroll
            for (int mt = 0; mt < 2; mt++)
                #pragma unroll
                for (int nt = 0; nt < 8; nt++) {
                    mma16816(o[mt][nt], pah[mt][ks2], fvh[nt >> 1][(nt & 1) * 2], fvh[nt >> 1][(nt & 1) * 2 + 1]);
                    mma16816(o[mt][nt], pah[mt][ks2], fvl[nt >> 1][(nt & 1) * 2], fvl[nt >> 1][(nt & 1) * 2 + 1]);
                    mma16816(o[mt][nt], pal[mt][ks2], fvh[nt >> 1][(nt & 1) * 2], fvh[nt >> 1][(nt & 1) * 2 + 1]);
                }
        }

        __syncthreads();
        if (kt + 2 < nkt) load_kv(kt + 2, kt & 1);
    }

    int b = bh >> 4, h = bh & 15;
    #pragma unroll
    for (int mt = 0; mt < 2; mt++) {
        float l0 = lsum[mt][0], l1 = lsum[mt][1];
        l0 += __shfl_xor_sync(0xFFFFFFFFu, l0, 1);
        l0 += __shfl_xor_sync(0xFFFFFFFFu, l0, 2);
        l1 += __shfl_xor_sync(0xFFFFFFFFu, l1, 1);
        l1 += __shfl_xor_sync(0xFFFFFFFFu, l1, 2);
        float inv0 = 1.0f / l0, inv1 = 1.0f / l1;

        int srow = qt * 128 + wid * 32 + mt * 16 + g;
        #pragma unroll
        for (int nt = 0; nt < 8; nt++) {
            int d = nt * 8 + t2;
            size_t o0 = (size_t)(b * SEQ + srow) * DIM + h * DH + d;
            size_t o1 = (size_t)(b * SEQ + srow + 8) * DIM + h * DH + d;
            uint32_t hi, lo;
            split2(o[mt][nt][0] * inv0, o[mt][nt][1] * inv0, hi, lo);
            *(uint32_t*)&Oh[o0] = hi;  *(uint32_t*)&Ol[o0] = lo;
            split2(o[mt][nt][2] * inv1, o[mt][nt][3] * inv1, hi, lo);
            *(uint32_t*)&Oh[o1] = hi;  *(uint32_t*)&Ol[o1] = lo;
        }
    }
}

// ===========================================================================
// Launch
// ===========================================================================
extern "C" void kernel_launch(void* const* d_in, const int* in_sizes, int n_in,
                              void* d_out, int out_size)
{
    (void)in_sizes; (void)n_in; (void)out_size;
    const float* x  = (const float*)d_in[0];
    const float* ns = (const float*)d_in[1];
    const float* Wq = (const float*)d_in[2];
    const float* Wk = (const float*)d_in[3];
    const float* Wv = (const float*)d_in[4];
    const float* Wo = (const float*)d_in[5];
    float* out = (float*)d_out;

    float *qkv, *sinT, *cosT;
    __nv_bfloat16 *ah, *al, *th, *tl, *qhp, *qlp, *khp, *klp, *vth, *vtl;
    cudaGetSymbolAddress((void**)&qkv, g_qkv);
    cudaGetSymbolAddress((void**)&sinT, g_sinT);
    cudaGetSymbolAddress((void**)&cosT, g_cosT);
    cudaGetSymbolAddress((void**)&ah, g_ah);
    cudaGetSymbolAddress((void**)&al, g_al);
    cudaGetSymbolAddress((void**)&th, g_th);
    cudaGetSymbolAddress((void**)&tl, g_tl);
    cudaGetSymbolAddress((void**)&qhp, g_qh);
    cudaGetSymbolAddress((void**)&qlp, g_ql);
    cudaGetSymbolAddress((void**)&khp, g_kh);
    cudaGetSymbolAddress((void**)&klp, g_kl);
    cudaGetSymbolAddress((void**)&vth, g_vth);
    cudaGetSymbolAddress((void**)&vtl, g_vtl);

    cudaFuncSetAttribute(mma_gemm_kernel,
                         cudaFuncAttributeMaxDynamicSharedMemorySize, GEMM_SMEM);
    cudaFuncSetAttribute(flash_mma_kernel,
                         cudaFuncAttributeMaxDynamicSharedMemorySize, FL_SMEM);

    prologue_kernel<<<dim3(DIM / 32, DIM / 32, 9), 256>>>(
        x, ns, Wq, Wk, Wv, Wo, th, tl, sinT, cosT, ah, al);

    mma_gemm_kernel<<<dim3(3 * (DIM / 128), ROWS / 256), 256, GEMM_SMEM>>>(
        ah, al, th, tl, qkv);

    qkv_prep_kernel<<<4096 + 4096, 256>>>(
        qkv, sinT, cosT, qhp, qlp, khp, klp, vth, vtl);

    flash_mma_kernel<<<dim3(SEQ / 128, BATCH * NH), 128, FL_SMEM>>>(
        qhp, qlp, khp, klp, vth, vtl, ah, al);

    mma_gemm_kernel<<<dim3(DIM / 128, ROWS / 256), 256, GEMM_SMEM>>>(
        ah, al, th + (size_t)3 * DIM * DIM, tl + (size_t)3 * DIM * DIM, out);
}

// round 16
// speedup vs baseline: 1.0366x; 1.0109x over previous
#include <cuda_runtime.h>
#include <cuda_bf16.h>
#include <stdint.h>
#include <math.h>

#define BATCH 2
#define SEQ   2048
#define DIM   1024
#define ROWS  (BATCH*SEQ)   // 4096
#define NH    16
#define DH    64

// Scratch (allocation-free rule: __device__ globals)
__device__ float g_qkv[3*ROWS*DIM];          // Q,K,V fp32 outputs
__device__ float g_sinT[SEQ*32];             // RoPE tables [pos][i]
__device__ float g_cosT[SEQ*32];
__device__ __nv_bfloat16 g_ah[ROWS*DIM];     // x_norm split hi; later attn-out hi
__device__ __nv_bfloat16 g_al[ROWS*DIM];     // x_norm split lo; later attn-out lo
__device__ __nv_bfloat16 g_th[4*DIM*DIM];    // W^T split hi [4][N][K] (q,k,v,o)
__device__ __nv_bfloat16 g_tl[4*DIM*DIM];    // W^T split lo
// attention operands, head-contiguous layouts
__device__ __nv_bfloat16 g_qh[ROWS*DIM];     // Q hi (roped) [bh][s][d]
__device__ __nv_bfloat16 g_ql[ROWS*DIM];
__device__ __nv_bfloat16 g_kh[ROWS*DIM];     // K hi (roped) [bh][s][d]
__device__ __nv_bfloat16 g_kl[ROWS*DIM];
__device__ __nv_bfloat16 g_vth[ROWS*DIM];    // V^T hi [bh][d][s]
__device__ __nv_bfloat16 g_vtl[ROWS*DIM];

// ===========================================================================
// Portable (compute_103-safe) PTX helpers: mma.sync / ldmatrix / cp.async
// ===========================================================================
__device__ __forceinline__ uint32_t smem_u32(const void* p) {
    uint32_t a;
    asm("{ .reg .u64 t; cvta.to.shared.u64 t, %1; cvt.u32.u64 %0, t; }"
        : "=r"(a) : "l"(p));
    return a;
}
__device__ __forceinline__ void cp_async16(uint32_t saddr, const void* gaddr) {
    asm volatile("cp.async.cg.shared.global [%0], [%1], 16;"
                 :: "r"(saddr), "l"(gaddr));
}
__device__ __forceinline__ void cp_commit() {
    asm volatile("cp.async.commit_group;" ::: "memory");
}
__device__ __forceinline__ void ldsm4(uint32_t* r, uint32_t addr) {
    asm volatile("ldmatrix.sync.aligned.m8n8.x4.shared.b16 {%0,%1,%2,%3}, [%4];"
                 : "=r"(r[0]), "=r"(r[1]), "=r"(r[2]), "=r"(r[3]) : "r"(addr));
}
__device__ __forceinline__ void mma16816(float* c, const uint32_t* a,
                                         uint32_t b0, uint32_t b1) {
    asm volatile(
        "mma.sync.aligned.m16n8k16.row.col.f32.bf16.bf16.f32 "
        "{%0,%1,%2,%3}, {%4,%5,%6,%7}, {%8,%9}, {%0,%1,%2,%3};"
        : "+f"(c[0]), "+f"(c[1]), "+f"(c[2]), "+f"(c[3])
        : "r"(a[0]), "r"(a[1]), "r"(a[2]), "r"(a[3]), "r"(b0), "r"(b1));
}
__device__ __forceinline__ uint32_t pack2h(__nv_bfloat16 a, __nv_bfloat16 b) {
    __nv_bfloat162 t = __halves2bfloat162(a, b);
    return *reinterpret_cast<uint32_t*>(&t);
}
__device__ __forceinline__ uint32_t pack2f(float a, float b) {
    __nv_bfloat162 t = __floats2bfloat162_rn(a, b);
    return *reinterpret_cast<uint32_t*>(&t);
}
__device__ __forceinline__ void split2(float a, float b, uint32_t& hi, uint32_t& lo) {
    __nv_bfloat16 ha = __float2bfloat16(a), hb = __float2bfloat16(b);
    hi = pack2h(ha, hb);
    lo = pack2f(a - __bfloat162float(ha), b - __bfloat162float(hb));
}
// exp(x*0.125) as a single FMUL + MUFU: ex2(x * 0.125*log2(e))
__device__ __forceinline__ float expq(float x) {
    float y;
    asm("ex2.approx.ftz.f32 %0, %1;" : "=f"(y) : "f"(x * 0.1803368801111244f));
    return y;
}

// ===========================================================================
// MERGED prologue (unchanged from R14/R15)
// ===========================================================================
__global__ __launch_bounds__(256) void prologue_kernel(
    const float* __restrict__ x, const float* __restrict__ sc,
    const float* __restrict__ W0, const float* __restrict__ W1,
    const float* __restrict__ W2, const float* __restrict__ W3,
    __nv_bfloat16* __restrict__ Th, __nv_bfloat16* __restrict__ Tl,
    float* __restrict__ sinT, float* __restrict__ cosT,
    __nv_bfloat16* __restrict__ ah, __nv_bfloat16* __restrict__ al)
{
    __shared__ float tile[32][33];
    __shared__ float red[256];
    int z = blockIdx.z;

    if (z == 4) {
        int idx = (blockIdx.y * 32 + blockIdx.x) * 256 + threadIdx.x;
        if (idx < SEQ * 32) {
            int pos = idx >> 5, i = idx & 31;
            float e = (2.0f * (float)i) / (float)DH;
            float theta = exp2f(-e * 19.931568569324174f);   // 1e6^-e
            float ang = (float)pos * theta;
            sinT[idx] = sinf(ang);
            cosT[idx] = cosf(ang);
        }
        return;
    }

    if (z >= 5) {
        int row = (z - 5) * 1024 + blockIdx.y * 32 + blockIdx.x;
        const float* xr = x + (size_t)row * DIM;
        float v[4];
        float ss = 0.f;
        #pragma unroll
        for (int j = 0; j < 4; j++) {
            v[j] = xr[threadIdx.x + j * 256];
            ss = fmaf(v[j], v[j], ss);
        }
        red[threadIdx.x] = ss;
        __syncthreads();
        #pragma unroll
        for (int s = 128; s > 0; s >>= 1) {
            if (threadIdx.x < s) red[threadIdx.x] += red[threadIdx.x + s];
            __syncthreads();
        }
        float r = rsqrtf(red[0] * (1.0f / DIM) + 1e-6f);
        #pragma unroll
        for (int j = 0; j < 4; j++) {
            int i = threadIdx.x + j * 256;
            float y = v[j] * r * sc[i];
            __nv_bfloat16 h = __float2bfloat16(y);
            ah[(size_t)row * DIM + i] = h;
            al[(size_t)row * DIM + i] = __float2bfloat16(y - __bfloat162float(h));
        }
        return;
    }

    const float* W = (z == 0) ? W0 : (z == 1) ? W1 : (z == 2) ? W2 : W3;
    __nv_bfloat16* th = Th + (size_t)z * DIM * DIM;
    __nv_bfloat16* tl = Tl + (size_t)z * DIM * DIM;

    int k0 = blockIdx.y * 32, n0 = blockIdx.x * 32;
    int tx = threadIdx.x & 31, ty = threadIdx.x >> 5;   // 32 x 8
    #pragma unroll
    for (int i = 0; i < 32; i += 8)
        tile[ty + i][tx] = W[(size_t)(k0 + ty + i) * DIM + n0 + tx];
    __syncthreads();
    #pragma unroll
    for (int i = 0; i < 32; i += 8) {
        float v = tile[tx][ty + i];    // = W[k0+tx][n0+ty+i]
        __nv_bfloat16 h = __float2bfloat16(v);
        float r = v - __bfloat162float(h);
        size_t o = (size_t)(n0 + ty + i) * DIM + k0 + tx;
        th[o] = h;
        tl[o] = __float2bfloat16(r);
    }
}

// ===========================================================================
// bf16-split GEMM via mma.sync. 3-stage cp.async pipeline (validated R10).
// ===========================================================================
#define A_TILE_B 20480             // 256 rows x 80 bytes
#define B_TILE_B 10240             // 128 rows x 80 bytes
#define STG_B    (2*A_TILE_B + 2*B_TILE_B)   // 61440
#define GEMM_SMEM (3*STG_B)                   // 184320 (3 stages)

__global__ __launch_bounds__(256) void mma_gemm_kernel(
    const __nv_bfloat16* __restrict__ Ah, const __nv_bfloat16* __restrict__ Al,
    const __nv_bfloat16* __restrict__ BhBase, const __nv_bfloat16* __restrict__ BlBase,
    float* __restrict__ CBase)
{
    extern __shared__ char smem[];
    uint32_t sb = smem_u32(smem);

    const int tid  = threadIdx.x;
    const int lane = tid & 31;
    const int wid  = tid >> 5;
    const int warp_m = wid & 3;
    const int warp_n = wid >> 2;
    const int which = blockIdx.x >> 3;               // weight index
    const int bm = blockIdx.y * 256;
    const int bn = (blockIdx.x & 7) * 128;

    const __nv_bfloat16* Bh = BhBase + (size_t)which * DIM * DIM;
    const __nv_bfloat16* Bl = BlBase + (size_t)which * DIM * DIM;
    float* C = CBase + (size_t)which * ROWS * DIM;

    float acc[4][8][4];
    #pragma unroll
    for (int i = 0; i < 4; i++)
        #pragma unroll
        for (int j = 0; j < 8; j++)
            #pragma unroll
            for (int q = 0; q < 4; q++) acc[i][j][q] = 0.f;

    auto load_stage = [&](int kt, int s) {
        const __nv_bfloat16* asrc[2] = {Ah, Al};
        #pragma unroll
        for (int t = 0; t < 2; t++) {
            #pragma unroll
            for (int i = 0; i < 4; i++) {
                int chunk = tid + i * 256;         // 0..1023
                int row = chunk >> 2, c = chunk & 3;
                cp_async16(sb + s * STG_B + t * A_TILE_B + row * 80 + c * 16,
                           asrc[t] + (size_t)(bm + row) * DIM + kt * 32 + c * 8);
            }
        }
        const __nv_bfloat16* bsrc[2] = {Bh, Bl};
        #pragma unroll
        for (int t = 0; t < 2; t++) {
            #pragma unroll
            for (int i = 0; i < 2; i++) {
                int chunk = tid + i * 256;         // 0..511
                int row = chunk >> 2, c = chunk & 3;
                cp_async16(sb + s * STG_B + 2 * A_TILE_B + t * B_TILE_B + row * 80 + c * 16,
                           bsrc[t] + (size_t)(bn + row) * DIM + kt * 32 + c * 8);
            }
        }
        cp_commit();
    };

    load_stage(0, 0);
    load_stage(1, 1);

    const int aRow = lane & 15;
    const int aK16 = (lane >> 4) * 16;
    const int bRow = (lane & 7) + ((lane >> 4) << 3);
    const int bK16 = ((lane >> 3) & 1) * 16;

    int sNext = 2;   // stage index for kt+2
    for (int kt = 0; kt < 32; kt++) {
        if (kt < 31) asm volatile("cp.async.wait_group 1;" ::: "memory");
        else         asm volatile("cp.async.wait_group 0;" ::: "memory");
        __syncthreads();

        if (kt + 2 < 32) load_stage(kt + 2, sNext);

        int sCur = sNext + 1; if (sCur >= 3) sCur -= 3;   // == kt % 3
        uint32_t st  = sb + sCur * STG_B;
        uint32_t aHb = st + (warp_m * 64 + aRow) * 80 + aK16;
        uint32_t aLb = aHb + A_TILE_B;
        uint32_t bHb = st + 2 * A_TILE_B + (warp_n * 64 + bRow) * 80 + bK16;
        uint32_t bLb = bHb + B_TILE_B;
        sNext = sCur;

        #pragma unroll
        for (int ks = 0; ks < 2; ks++) {
            uint32_t koff = ks * 32;
            uint32_t fah[4][4], fal[4][4], fb[4][4];
            #pragma unroll
            for (int mt = 0; mt < 4; mt++) {
                ldsm4(fah[mt], aHb + mt * 1280 + koff);
                ldsm4(fal[mt], aLb + mt * 1280 + koff);
            }
            #pragma unroll
            for (int n2 = 0; n2 < 4; n2++)
                ldsm4(fb[n2], bHb + n2 * 1280 + koff);
            #pragma unroll
            for (int mt = 0; mt < 4; mt++)
                #pragma unroll
                for (int nt = 0; nt < 8; nt++)
                    mma16816(acc[mt][nt], fah[mt],
                             fb[nt >> 1][(nt & 1) * 2], fb[nt >> 1][(nt & 1) * 2 + 1]);
            #pragma unroll
            for (int mt = 0; mt < 4; mt++)
                #pragma unroll
                for (int nt = 0; nt < 8; nt++)
                    mma16816(acc[mt][nt], fal[mt],
                             fb[nt >> 1][(nt & 1) * 2], fb[nt >> 1][(nt & 1) * 2 + 1]);
            #pragma unroll
            for (int n2 = 0; n2 < 4; n2++)
                ldsm4(fb[n2], bLb + n2 * 1280 + koff);
            #pragma unroll
            for (int mt = 0; mt < 4; mt++)
                #pragma unroll
                for (int nt = 0; nt < 8; nt++)
                    mma16816(acc[mt][nt], fah[mt],
                             fb[nt >> 1][(nt & 1) * 2], fb[nt >> 1][(nt & 1) * 2 + 1]);
        }
    }

    const int g = lane >> 2, t2 = (lane & 3) * 2;
    #pragma unroll
    for (int mt = 0; mt < 4; mt++) {
        #pragma unroll
        for (int nt = 0; nt < 8; nt++) {
            int row = bm + warp_m * 64 + mt * 16 + g;
            int col = bn + warp_n * 64 + nt * 8 + t2;
            *(float2*)&C[(size_t)row * DIM + col] =
                make_float2(acc[mt][nt][0], acc[mt][nt][1]);
            *(float2*)&C[(size_t)(row + 8) * DIM + col] =
                make_float2(acc[mt][nt][2], acc[mt][nt][3]);
        }
    }
}

// ===========================================================================
// Merged RoPE-split (float4 vectorized) + V transpose-split (4B stores).
// ===========================================================================
__global__ __launch_bounds__(256) void qkv_prep_kernel(
    const float* __restrict__ qkv,
    const float* __restrict__ sinT, const float* __restrict__ cosT,
    __nv_bfloat16* __restrict__ Qh, __nv_bfloat16* __restrict__ Ql,
    __nv_bfloat16* __restrict__ Kh, __nv_bfloat16* __restrict__ Kl,
    __nv_bfloat16* __restrict__ Vth, __nv_bfloat16* __restrict__ Vtl)
{
    __shared__ float tile[32][33];
    int bid = blockIdx.x;

    if (bid < 4096) {
        int idx = bid * 256 + threadIdx.x;     // 2^20 total
        int which = idx >> 19;                 // 0=q, 1=k
        int r   = idx & ((1 << 19) - 1);
        int row = r >> 7;                      // 128 = 16 heads * 8
        int rem = r & 127;
        int head = rem >> 3;
        int i4   = (rem & 7) * 4;

        const float* src = qkv + (size_t)which * ROWS * DIM
                               + (size_t)row * DIM + head * DH;
        int pos = row & (SEQ - 1);

        float4 sn = *(const float4*)&sinT[pos * 32 + i4];
        float4 cs = *(const float4*)&cosT[pos * 32 + i4];
        float4 x1 = *(const float4*)&src[i4];
        float4 x2 = *(const float4*)&src[i4 + 32];

        float y1a = x1.x * cs.x - x2.x * sn.x, y2a = x1.x * sn.x + x2.x * cs.x;
        float y1b = x1.y * cs.y - x2.y * sn.y, y2b = x1.y * sn.y + x2.y * cs.y;
        float y1c = x1.z * cs.z - x2.z * sn.z, y2c = x1.z * sn.z + x2.z * cs.z;
        float y1d = x1.w * cs.w - x2.w * sn.w, y2d = x1.w * sn.w + x2.w * cs.w;

        int b = row >> 11, s = row & (SEQ - 1);
        size_t o = ((size_t)(b * NH + head) * SEQ + s) * DH + i4;
        __nv_bfloat16* H = which ? Kh : Qh;
        __nv_bfloat16* L = which ? Kl : Ql;
        uint32_t h0, l0, h1, l1;
        split2(y1a, y1b, h0, l0);
        split2(y1c, y1d, h1, l1);
        *(uint2*)&H[o] = make_uint2(h0, h1);
        *(uint2*)&L[o] = make_uint2(l0, l1);
        split2(y2a, y2b, h0, l0);
        split2(y2c, y2d, h1, l1);
        *(uint2*)&H[o + 32] = make_uint2(h0, h1);
        *(uint2*)&L[o + 32] = make_uint2(l0, l1);
    } else {
        int b2 = bid - 4096;                 // [0, 4096)
        int s0 = (b2 & 63) * 32;
        int d0 = ((b2 >> 6) & 1) * 32;
        int bh = b2 >> 7;
        int b = bh >> 4, h = bh & 15;
        const float* v = qkv + (size_t)2 * ROWS * DIM;
        int tx = threadIdx.x & 31, ty = threadIdx.x >> 5;
        #pragma unroll
        for (int i = 0; i < 32; i += 8)
            tile[ty + i][tx] = v[(size_t)(b * SEQ + s0 + ty + i) * DIM + h * DH + d0 + tx];
        __syncthreads();
        int sx = threadIdx.x & 15;
        int dy = threadIdx.x >> 4;
        #pragma unroll
        for (int dd = 0; dd < 32; dd += 16) {
            int d = dy + dd;
            float va = tile[sx * 2][d];
            float vb = tile[sx * 2 + 1][d];
            uint32_t hi, lo;
            split2(va, vb, hi, lo);
            size_t o = ((size_t)(bh * DH + d0 + d)) * SEQ + s0 + sx * 2;
            *(uint32_t*)&Vth[o] = hi;
            *(uint32_t*)&Vtl[o] = lo;
        }
    }
}

// ===========================================================================
// Flash attention via mma.sync, split-bf16.
// 4 warps x 32 q-rows (2 m-tiles/warp), 128 threads, 2 CTAs/SM, 2-stage KV.
// Register relief: single predicated softmax path; Q-lo fragments reloaded
// from (persistent) Q smem per chunk instead of staying register-resident.
// ===========================================================================
#define FP      144                 // smem row pitch (bytes)
#define FQ_OFF  0                   // Qh @0, Ql @18432 (128 rows x 144)
#define FK_OFF  36864               // + stage*18432; Kh +0, Kl +9216
#define FV_OFF  73728               // + stage*18432; Vh +0, Vl +9216
#define FL_SMEM 110592

__global__ __launch_bounds__(128, 2) void flash_mma_kernel(
    const __nv_bfloat16* __restrict__ Qh_, const __nv_bfloat16* __restrict__ Ql_,
    const __nv_bfloat16* __restrict__ Kh_, const __nv_bfloat16* __restrict__ Kl_,
    const __nv_bfloat16* __restrict__ Vth_, const __nv_bfloat16* __restrict__ Vtl_,
    __nv_bfloat16* __restrict__ Oh, __nv_bfloat16* __restrict__ Ol)
{
    extern __shared__ char smem[];
    uint32_t sb = smem_u32(smem);
    const int tid = threadIdx.x, lane = tid & 31, wid = tid >> 5;   // wid 0..3
    const int bh = blockIdx.y;
    const int qt = (gridDim.x - 1) - blockIdx.x;   // heavy tiles first
    const int nkt = 2 * (qt + 1);                  // 64-key chunks
    const size_t qkoff = (size_t)bh * SEQ * DH;
    const size_t voff  = (size_t)bh * DH * SEQ;

    // Q tile load (once; region persists the whole kernel)
    {
        const __nv_bfloat16* qs[2] = {Qh_ + qkoff, Ql_ + qkoff};
        #pragma unroll
        for (int i = 0; i < 16; i++) {
            int idx = tid + i * 128;           // 0..2047
            int t = idx >> 10, rem = idx & 1023;
            int row = rem >> 3, c = rem & 7;
            cp_async16(sb + FQ_OFF + t * 18432 + row * FP + c * 16,
                       qs[t] + (size_t)(qt * 128 + row) * DH + c * 8);
        }
        cp_commit();
    }

    auto load_kv = [&](int kt, int s) {
        int k0 = kt * 64;
        const __nv_bfloat16* ks_[2] = {Kh_ + qkoff, Kl_ + qkoff};
        const __nv_bfloat16* vs_[2] = {Vth_ + voff, Vtl_ + voff};
        #pragma unroll
        for (int i = 0; i < 8; i++) {
            int idx = tid + i * 128;           // 0..1023
            int t = idx >> 9, rem = idx & 511;
            int row = rem >> 3, c = rem & 7;
            cp_async16(sb + FK_OFF + s * 18432 + t * 9216 + row * FP + c * 16,
                       ks_[t] + (size_t)(k0 + row) * DH + c * 8);
        }
        #pragma unroll
        for (int i = 0; i < 8; i++) {
            int idx = tid + i * 128;
            int t = idx >> 9, rem = idx & 511;
            int row = rem >> 3, c = rem & 7;   // row = dh index, c = key chunk
            cp_async16(sb + FV_OFF + s * 18432 + t * 9216 + row * FP + c * 16,
                       vs_[t] + (size_t)row * SEQ + k0 + c * 8);
        }
        cp_commit();
    };
    load_kv(0, 0);
    load_kv(1, 1);

    const int g = lane >> 2, t2 = (lane & 3) * 2;
    const int aRow = lane & 15, aK16 = (lane >> 4) * 16;
    const int bRow = (lane & 7) + ((lane >> 4) << 3);
    const int bK16 = ((lane >> 3) & 1) * 16;

    asm volatile("cp.async.wait_group 2;" ::: "memory");
    __syncthreads();

    // Q-hi fragments resident; Q-lo reloaded from smem each chunk.
    uint32_t qh[2][4][4];
    uint32_t qbase[2];
    #pragma unroll
    for (int mt = 0; mt < 2; mt++) {
        qbase[mt] = sb + FQ_OFF + (wid * 32 + mt * 16 + aRow) * FP + aK16;
        #pragma unroll
        for (int ks = 0; ks < 4; ks++)
            ldsm4(qh[mt][ks], qbase[mt] + ks * 32);
    }

    float o[2][8][4];
    #pragma unroll
    for (int mt = 0; mt < 2; mt++)
        #pragma unroll
        for (int nt = 0; nt < 8; nt++)
            #pragma unroll
            for (int j = 0; j < 4; j++) o[mt][nt][j] = 0.f;
    float lsum[2][2] = {{0.f, 0.f}, {0.f, 0.f}};
    const int rowW = qt * 128 + wid * 32;   // warp-uniform base row

    for (int kt = 0; kt < nkt; kt++) {
        if (kt < nkt - 1) asm volatile("cp.async.wait_group 1;" ::: "memory");
        else              asm volatile("cp.async.wait_group 0;" ::: "memory");
        __syncthreads();

        uint32_t stK = sb + FK_OFF + (kt & 1) * 18432;
        uint32_t stV = sb + FV_OFF + (kt & 1) * 18432;

        // ---- S = Q K^T, both m-tiles share each K fragment load ----
        float S[2][8][4];
        #pragma unroll
        for (int mt = 0; mt < 2; mt++)
            #pragma unroll
            for (int nt = 0; nt < 8; nt++)
                #pragma unroll
                for (int j = 0; j < 4; j++) S[mt][nt][j] = 0.f;

        #pragma unroll
        for (int ks = 0; ks < 4; ks++) {
            uint32_t fkh[4][4], fkl[4][4];
            #pragma unroll
            for (int n2 = 0; n2 < 4; n2++) {
                uint32_t a = stK + (n2 * 16 + bRow) * FP + bK16 + ks * 32;
                ldsm4(fkh[n2], a);
                ldsm4(fkl[n2], a + 9216);
            }
            #pragma unroll
            for (int mt = 0; mt < 2; mt++) {
                uint32_t qlf[4];
                ldsm4(qlf, qbase[mt] + 18432 + ks * 32);   // Q-lo from smem
                #pragma unroll
                for (int nt = 0; nt < 8; nt++) {
                    mma16816(S[mt][nt], qh[mt][ks], fkh[nt >> 1][(nt & 1) * 2], fkh[nt >> 1][(nt & 1) * 2 + 1]);
                    mma16816(S[mt][nt], qh[mt][ks], fkl[nt >> 1][(nt & 1) * 2], fkl[nt >> 1][(nt & 1) * 2 + 1]);
                    mma16816(S[mt][nt], qlf,        fkh[nt >> 1][(nt & 1) * 2], fkh[nt >> 1][(nt & 1) * 2 + 1]);
                }
            }
        }

        // ---- softmax + pack P (single predicated path) ----
        uint32_t pah[2][4][4], pal[2][4][4];
        int k0 = kt * 64;
        #pragma unroll
        for (int mt = 0; mt < 2; mt++) {
            int row0 = rowW + mt * 16 + g;
            #pragma unroll
            for (int nt = 0; nt < 8; nt++) {
                int col = k0 + nt * 8 + t2;
                float p0 = (col     <= row0)     ? expq(S[mt][nt][0]) : 0.f;
                float p1 = (col + 1 <= row0)     ? expq(S[mt][nt][1]) : 0.f;
                float p2 = (col     <= row0 + 8) ? expq(S[mt][nt][2]) : 0.f;
                float p3 = (col + 1 <= row0 + 8) ? expq(S[mt][nt][3]) : 0.f;
                lsum[mt][0] += p0 + p1;
                lsum[mt][1] += p2 + p3;
                __nv_bfloat16 h0 = __float2bfloat16(p0), h1 = __float2bfloat16(p1);
                __nv_bfloat16 h2 = __float2bfloat16(p2), h3 = __float2bfloat16(p3);
                float r0 = p0 - __bfloat162float(h0), r1 = p1 - __bfloat162float(h1);
                float r2 = p2 - __bfloat162float(h2), r3 = p3 - __bfloat162float(h3);
                int ks2 = nt >> 1, off = (nt & 1) * 2;
                pah[mt][ks2][off]     = pack2h(h0, h1);
                pah[mt][ks2][off + 1] = pack2h(h2, h3);
                pal[mt][ks2][off]     = pack2f(r0, r1);
                pal[mt][ks2][off + 1] = pack2f(r2, r3);
            }
        }

        // ---- O += P V, both m-tiles share each V fragment load ----
        #pragma unroll
        for (int ks2 = 0; ks2 < 4; ks2++) {
            uint32_t fvh[4][4], fvl[4][4];
            #pragma unroll
            for (int n2 = 0; n2 < 4; n2++) {
                uint32_t a = stV + (n2 * 16 + bRow) * FP + bK16 + ks2 * 32;
                ldsm4(fvh[n2], a);
                ldsm4(fvl[n2], a + 9216);
            }
            #pragma unroll
            for (int mt = 0; mt < 2; mt++)
                #pragma unroll
                for (int nt = 0; nt < 8; nt++) {
                    mma16816(o[mt][nt], pah[mt][ks2], fvh[nt >> 1][(nt & 1) * 2], fvh[nt >> 1][(nt & 1) * 2 + 1]);
                    mma16816(o[mt][nt], pah[mt][ks2], fvl[nt >> 1][(nt & 1) * 2], fvl[nt >> 1][(nt & 1) * 2 + 1]);
                    mma16816(o[mt][nt], pal[mt][ks2], fvh[nt >> 1][(nt & 1) * 2], fvh[nt >> 1][(nt & 1) * 2 + 1]);
                }
        }

        __syncthreads();
        if (kt + 2 < nkt) load_kv(kt + 2, kt & 1);
    }

    int b = bh >> 4, h = bh & 15;
    #pragma unroll
    for (int mt = 0; mt < 2; mt++) {
        float l0 = lsum[mt][0], l1 = lsum[mt][1];
        l0 += __shfl_xor_sync(0xFFFFFFFFu, l0, 1);
        l0 += __shfl_xor_sync(0xFFFFFFFFu, l0, 2);
        l1 += __shfl_xor_sync(0xFFFFFFFFu, l1, 1);
        l1 += __shfl_xor_sync(0xFFFFFFFFu, l1, 2);
        float inv0 = 1.0f / l0, inv1 = 1.0f / l1;

        int srow = qt * 128 + wid * 32 + mt * 16 + g;
        #pragma unroll
        for (int nt = 0; nt < 8; nt++) {
            int d = nt * 8 + t2;
            size_t o0 = (size_t)(b * SEQ + srow) * DIM + h * DH + d;
            size_t o1 = (size_t)(b * SEQ + srow + 8) * DIM + h * DH + d;
            uint32_t hi, lo;
            split2(o[mt][nt][0] * inv0, o[mt][nt][1] * inv0, hi, lo);
            *(uint32_t*)&Oh[o0] = hi;  *(uint32_t*)&Ol[o0] = lo;
            split2(o[mt][nt][2] * inv1, o[mt][nt][3] * inv1, hi, lo);
            *(uint32_t*)&Oh[o1] = hi;  *(uint32_t*)&Ol[o1] = lo;
        }
    }
}

// ===========================================================================
// Launch
// ===========================================================================
extern "C" void kernel_launch(void* const* d_in, const int* in_sizes, int n_in,
                              void* d_out, int out_size)
{
    (void)in_sizes; (void)n_in; (void)out_size;
    const float* x  = (const float*)d_in[0];
    const float* ns = (const float*)d_in[1];
    const float* Wq = (const float*)d_in[2];
    const float* Wk = (const float*)d_in[3];
    const float* Wv = (const float*)d_in[4];
    const float* Wo = (const float*)d_in[5];
    float* out = (float*)d_out;

    float *qkv, *sinT, *cosT;
    __nv_bfloat16 *ah, *al, *th, *tl, *qhp, *qlp, *khp, *klp, *vth, *vtl;
    cudaGetSymbolAddress((void**)&qkv, g_qkv);
    cudaGetSymbolAddress((void**)&sinT, g_sinT);
    cudaGetSymbolAddress((void**)&cosT, g_cosT);
    cudaGetSymbolAddress((void**)&ah, g_ah);
    cudaGetSymbolAddress((void**)&al, g_al);
    cudaGetSymbolAddress((void**)&th, g_th);
    cudaGetSymbolAddress((void**)&tl, g_tl);
    cudaGetSymbolAddress((void**)&qhp, g_qh);
    cudaGetSymbolAddress((void**)&qlp, g_ql);
    cudaGetSymbolAddress((void**)&khp, g_kh);
    cudaGetSymbolAddress((void**)&klp, g_kl);
    cudaGetSymbolAddress((void**)&vth, g_vth);
    cudaGetSymbolAddress((void**)&vtl, g_vtl);

    cudaFuncSetAttribute(mma_gemm_kernel,
                         cudaFuncAttributeMaxDynamicSharedMemorySize, GEMM_SMEM);
    cudaFuncSetAttribute(flash_mma_kernel,
                         cudaFuncAttributeMaxDynamicSharedMemorySize, FL_SMEM);

    prologue_kernel<<<dim3(DIM / 32, DIM / 32, 9), 256>>>(
        x, ns, Wq, Wk, Wv, Wo, th, tl, sinT, cosT, ah, al);

    mma_gemm_kernel<<<dim3(3 * (DIM / 128), ROWS / 256), 256, GEMM_SMEM>>>(
        ah, al, th, tl, qkv);

    qkv_prep_kernel<<<4096 + 4096, 256>>>(
        qkv, sinT, cosT, qhp, qlp, khp, klp, vth, vtl);

    flash_mma_kernel<<<dim3(SEQ / 128, BATCH * NH), 128, FL_SMEM>>>(
        qhp, qlp, khp, klp, vth, vtl, ah, al);

    mma_gemm_kernel<<<dim3(DIM / 128, ROWS / 256), 256, GEMM_SMEM>>>(
        ah, al, th + (size_t)3 * DIM * DIM, tl + (size_t)3 * DIM * DIM, out);
}